// round 3
// baseline (speedup 1.0000x reference)
#include <cuda_runtime.h>
#include <cstdint>

#define NN 50000
#define NE 800000
#define NG 64
#define MAXF 128

// ---------------- scratch (device globals; no runtime allocation) ----------------
__device__ __align__(16) float g_bufA[NN * MAXF];
__device__ __align__(16) float g_bufB[NN * MAXF];
__device__ __align__(16) float g_h[NN * MAXF];
__device__ float g_norm[NE];
__device__ int   g_src[NE];
__device__ int   g_dst[NE];
__device__ float g_deg[NN];
__device__ float g_dinv[NN];
__device__ float g_invdeg[NN];
__device__ __align__(16) float g_pool[NG * 32];
__device__ float g_cnt[NG];
__device__ unsigned int g_maxbits;
__device__ unsigned int g_oddOr;   // OR of odd 32-bit words of edge_index; 0 -> int64 layout

__device__ __forceinline__ float* bufptr(int i) {
    return (i == 0) ? g_bufA : ((i == 1) ? g_bufB : g_h);
}

// ---------------- init: zero accumulators ----------------
__global__ void k_init() {
    int i = blockIdx.x * blockDim.x + threadIdx.x;
    if (i < NN) g_deg[i] = 0.f;
    if (i < NG * 32) g_pool[i] = 0.f;
    if (i < NG) g_cnt[i] = 0.f;
    if (i == 0) { g_maxbits = 0u; g_oddOr = 0u; }
}

// ---------------- dtype detection: OR odd 32-bit words of first 2*NE words ----------------
// int64 data (values < 2^31): odd words are zero high-halves -> OR == 0.
// int32 data: odd words are node indices -> OR != 0 (w.h.p. over 800k words).
__global__ void k_detect(const unsigned int* __restrict__ ei32) {
    unsigned int v = 0;
    for (int i = blockIdx.x * blockDim.x + threadIdx.x; i < NE;
         i += gridDim.x * blockDim.x)
        v |= ei32[2 * i + 1];
#pragma unroll
    for (int o = 16; o; o >>= 1) v |= __shfl_xor_sync(0xffffffffu, v, o);
    if ((threadIdx.x & 31) == 0 && v) atomicOr(&g_oddOr, v);
}

// ---------------- max(edge_attr) (all values >= 0 so uint-bit max works) ----------------
__global__ void k_max(const float* __restrict__ ea) {
    float m = 0.f;
    for (int i = blockIdx.x * blockDim.x + threadIdx.x; i < NE;
         i += gridDim.x * blockDim.x)
        m = fmaxf(m, ea[i]);
#pragma unroll
    for (int o = 16; o; o >>= 1) m = fmaxf(m, __shfl_xor_sync(0xffffffffu, m, o));
    __shared__ float sm[8];
    if ((threadIdx.x & 31) == 0) sm[threadIdx.x >> 5] = m;
    __syncthreads();
    if (threadIdx.x < 8) {
        m = sm[threadIdx.x];
#pragma unroll
        for (int o = 4; o; o >>= 1) m = fmaxf(m, __shfl_xor_sync(0xffu, m, o));
        if (threadIdx.x == 0) atomicMax(&g_maxbits, __float_as_uint(m));
    }
}

// ---------------- per-edge: decode indices, weighted degree accumulation ----------------
__global__ void k_deg(const void* __restrict__ ei, const float* __restrict__ ea) {
    int e = blockIdx.x * blockDim.x + threadIdx.x;
    if (e >= NE) return;
    int s, d;
    if (g_oddOr == 0u) {  // int64 layout
        const long long* p = (const long long*)ei;
        s = (int)p[e];
        d = (int)p[NE + e];
    } else {              // int32 layout
        const int* p = (const int*)ei;
        s = p[e];
        d = p[NE + e];
    }
    g_src[e] = s;
    g_dst[e] = d;
    float maxv = __uint_as_float(g_maxbits);
    float w = ea[e] / maxv;
    atomicAdd(&g_deg[d], w);
}

// ---------------- per-node: dinv = rsqrt(deg+1), invdeg = 1/(deg+1) ----------------
__global__ void k_node() {
    int i = blockIdx.x * blockDim.x + threadIdx.x;
    if (i >= NN) return;
    float d = g_deg[i] + 1.f;
    g_dinv[i] = rsqrtf(d);
    g_invdeg[i] = 1.f / d;
}

// ---------------- per-edge: norm = dinv[src] * w * dinv[dst] ----------------
__global__ void k_norm(const float* __restrict__ ea) {
    int e = blockIdx.x * blockDim.x + threadIdx.x;
    if (e >= NE) return;
    float maxv = __uint_as_float(g_maxbits);
    float w = ea[e] / maxv;
    g_norm[e] = g_dinv[g_src[e]] * w * g_dinv[g_dst[e]];
}

// ---------------- tiled fp32 GEMM with fused epilogue ----------------
// H = act(A) @ W ;  AGG = H * invdeg[row] + bias[col]
__global__ void k_gemm(const float* __restrict__ Aext, int ainIdx,
                       const float* __restrict__ W, const float* __restrict__ bias,
                       int aggIdx, int M, int K, int N, int reluIn) {
    __shared__ float As[64][17];
    __shared__ float Bs[16][65];
    const float* A = (ainIdx < 0) ? Aext : bufptr(ainIdx);
    float* H = g_h;
    float* AGG = bufptr(aggIdx);

    int tid = threadIdx.x;
    int tx = tid & 15, ty = tid >> 4;
    int rowBase = blockIdx.y * 64;
    int colBase = blockIdx.x * 64;

    float acc[4][4];
#pragma unroll
    for (int i = 0; i < 4; i++)
#pragma unroll
        for (int j = 0; j < 4; j++) acc[i][j] = 0.f;

    int la_r = tid >> 2;          // 0..63
    int la_c = (tid & 3) * 4;     // 0,4,8,12
    int lb_r = tid >> 4;          // 0..15
    int lb_c = (tid & 15) * 4;    // 0..60

    for (int kt = 0; kt < K; kt += 16) {
        int ar = rowBase + la_r;
        float4 va = make_float4(0.f, 0.f, 0.f, 0.f);
        if (ar < M)
            va = *(const float4*)(A + (size_t)ar * K + kt + la_c);
        if (reluIn) {
            va.x = fmaxf(va.x, 0.f); va.y = fmaxf(va.y, 0.f);
            va.z = fmaxf(va.z, 0.f); va.w = fmaxf(va.w, 0.f);
        }
        As[la_r][la_c + 0] = va.x; As[la_r][la_c + 1] = va.y;
        As[la_r][la_c + 2] = va.z; As[la_r][la_c + 3] = va.w;

        int bc = colBase + lb_c;
        float4 vb = make_float4(0.f, 0.f, 0.f, 0.f);
        if (bc < N)
            vb = *(const float4*)(W + (size_t)(kt + lb_r) * N + bc);
        Bs[lb_r][lb_c + 0] = vb.x; Bs[lb_r][lb_c + 1] = vb.y;
        Bs[lb_r][lb_c + 2] = vb.z; Bs[lb_r][lb_c + 3] = vb.w;

        __syncthreads();
#pragma unroll
        for (int kk = 0; kk < 16; kk++) {
            float a[4], b[4];
#pragma unroll
            for (int i = 0; i < 4; i++) a[i] = As[ty * 4 + i][kk];
#pragma unroll
            for (int j = 0; j < 4; j++) b[j] = Bs[kk][tx * 4 + j];
#pragma unroll
            for (int i = 0; i < 4; i++)
#pragma unroll
                for (int j = 0; j < 4; j++) acc[i][j] = fmaf(a[i], b[j], acc[i][j]);
        }
        __syncthreads();
    }

#pragma unroll
    for (int i = 0; i < 4; i++) {
        int r = rowBase + ty * 4 + i;
        if (r >= M) continue;
        float id = g_invdeg[r];
#pragma unroll
        for (int j = 0; j < 4; j++) {
            int c = colBase + tx * 4 + j;
            if (c >= N) continue;
            float h = acc[i][j];
            H[(size_t)r * N + c] = h;
            AGG[(size_t)r * N + c] = fmaf(h, id, bias[c]);
        }
    }
}

// ---------------- edge scatter: AGG[dst] += norm * H[src] ----------------
__global__ void k_scatter(int aggIdx, int vecShift) {
    int VEC = 1 << vecShift;  // float4 chunks per node row
    int t = blockIdx.x * blockDim.x + threadIdx.x;
    if (t >= (NE << vecShift)) return;
    int e = t >> vecShift;
    int j = t & (VEC - 1);
    float nrm = g_norm[e];
    const float4* H4 = (const float4*)g_h;
    float* AGG = bufptr(aggIdx);
    float4 v = H4[(size_t)g_src[e] * VEC + j];
    float* p = AGG + ((size_t)g_dst[e] * VEC + j) * 4;
    atomicAdd(p + 0, v.x * nrm);
    atomicAdd(p + 1, v.y * nrm);
    atomicAdd(p + 2, v.z * nrm);
    atomicAdd(p + 3, v.w * nrm);
}

// ---------------- pooling: relu then segment-sum into per-graph accumulators ----------------
__global__ void k_pool(int aggIdx, const void* __restrict__ batch) {
    int t = blockIdx.x * blockDim.x + threadIdx.x;
    if (t >= NN * 8) return;
    int n = t >> 3, j = t & 7;
    int g;
    if (g_oddOr == 0u) g = (int)((const long long*)batch)[n];
    else               g = ((const int*)batch)[n];
    const float4* A4 = (const float4*)bufptr(aggIdx);
    float4 v = A4[(size_t)n * 8 + j];
    float* p = &g_pool[g * 32 + j * 4];
    atomicAdd(p + 0, fmaxf(v.x, 0.f));
    atomicAdd(p + 1, fmaxf(v.y, 0.f));
    atomicAdd(p + 2, fmaxf(v.z, 0.f));
    atomicAdd(p + 3, fmaxf(v.w, 0.f));
    if (j == 0) atomicAdd(&g_cnt[g], 1.f);
}

// ---------------- head: out[g] = (pool_sum[g]/max(cnt,1)) @ Wl + bl ----------------
__global__ void k_out(const float* __restrict__ Wl, const float* __restrict__ bl,
                      float* __restrict__ out) {
    __shared__ float pooled[32];
    int g = blockIdx.x;
    if (threadIdx.x < 32) {
        float c = g_cnt[g];
        pooled[threadIdx.x] = g_pool[g * 32 + threadIdx.x] / fmaxf(c, 1.f);
    }
    __syncthreads();
    int o = threadIdx.x;  // 768 threads
    float acc = bl[o];
#pragma unroll
    for (int c = 0; c < 32; c++) acc = fmaf(pooled[c], Wl[c * 768 + o], acc);
    out[(size_t)g * 768 + o] = acc;
}

// ---------------- launch ----------------
extern "C" void kernel_launch(void* const* d_in, const int* in_sizes, int n_in,
                              void* d_out, int out_size) {
    const float* x = (const float*)d_in[0];
    const void* ei = d_in[1];
    const float* ea = (const float*)d_in[2];
    const void* batch = d_in[3];
    const float* W1 = (const float*)d_in[4];
    const float* b1 = (const float*)d_in[5];
    const float* W2 = (const float*)d_in[6];
    const float* b2 = (const float*)d_in[7];
    const float* W3 = (const float*)d_in[8];
    const float* b3 = (const float*)d_in[9];
    const float* Wl = (const float*)d_in[10];
    const float* bl = (const float*)d_in[11];
    float* out = (float*)d_out;

    k_init<<<(NN + 255) / 256, 256>>>();
    k_detect<<<256, 256>>>((const unsigned int*)ei);
    k_max<<<512, 256>>>(ea);
    k_deg<<<(NE + 255) / 256, 256>>>(ei, ea);
    k_node<<<(NN + 255) / 256, 256>>>();
    k_norm<<<(NE + 255) / 256, 256>>>(ea);

    // Layer 1: x[50000,128] @ W1[128,128]; agg -> bufA(0)
    {
        dim3 grid((128 + 63) / 64, (NN + 63) / 64);
        k_gemm<<<grid, 256>>>(x, -1, W1, b1, /*agg=*/0, NN, 128, 128, /*relu=*/0);
        int vecShift = 5;  // 32 float4 per edge
        int total = NE << vecShift;
        k_scatter<<<(total + 255) / 256, 256>>>(/*agg=*/0, vecShift);
    }
    // Layer 2: relu(bufA)[50000,128] @ W2[128,64]; agg -> bufB(1)
    {
        dim3 grid((64 + 63) / 64, (NN + 63) / 64);
        k_gemm<<<grid, 256>>>(nullptr, 0, W2, b2, /*agg=*/1, NN, 128, 64, /*relu=*/1);
        int vecShift = 4;  // 16 float4 per edge
        int total = NE << vecShift;
        k_scatter<<<(total + 255) / 256, 256>>>(/*agg=*/1, vecShift);
    }
    // Layer 3: relu(bufB)[50000,64] @ W3[64,32]; agg -> bufA(0)
    {
        dim3 grid((32 + 63) / 64, (NN + 63) / 64);
        k_gemm<<<grid, 256>>>(nullptr, 1, W3, b3, /*agg=*/0, NN, 64, 32, /*relu=*/1);
        int vecShift = 3;  // 8 float4 per edge
        int total = NE << vecShift;
        k_scatter<<<(total + 255) / 256, 256>>>(/*agg=*/0, vecShift);
    }
    // Pool (relu fused) + head
    k_pool<<<(NN * 8 + 255) / 256, 256>>>(/*agg=*/0, batch);
    k_out<<<NG, 768>>>(Wl, bl, out);
}

// round 4
// speedup vs baseline: 1.9019x; 1.9019x over previous
#include <cuda_runtime.h>
#include <cstdint>

#define NN 50000
#define NE 800000
#define NG 64
#define MAXF 128
#define SCAN_BLK 256
#define NBLK ((NN + SCAN_BLK - 1) / SCAN_BLK)   // 196

// ---------------- scratch (device globals; no runtime allocation) ----------------
__device__ __align__(16) float g_bufA[NN * MAXF];
__device__ __align__(16) float g_bufB[NN * MAXF];
__device__ __align__(16) float g_h[NN * MAXF];
__device__ int   g_src[NE];
__device__ int   g_dst[NE];
__device__ int   g_csrc[NE];     // CSR-permuted src
__device__ float g_cnorm[NE];    // CSR-permuted norm
__device__ int   g_count[NN];    // in-degree (unweighted)
__device__ int   g_rowptr[NN + 1];
__device__ int   g_fill[NN];
__device__ int   g_blocksum[NBLK + 1];
__device__ float g_deg[NN];
__device__ float g_dinv[NN];
__device__ float g_invdeg[NN];
__device__ __align__(16) float g_pool[NG * 32];
__device__ float g_cnt[NG];
__device__ unsigned int g_maxbits;
__device__ unsigned int g_oddOr;   // 0 -> edge_index/batch are int64, else int32

__device__ __forceinline__ float* bufptr(int i) {
    return (i == 0) ? g_bufA : ((i == 1) ? g_bufB : g_h);
}

// ---------------- init: zero accumulators ----------------
__global__ void k_init() {
    int i = blockIdx.x * blockDim.x + threadIdx.x;
    if (i < NN) { g_deg[i] = 0.f; g_count[i] = 0; g_fill[i] = 0; }
    if (i < NG * 32) g_pool[i] = 0.f;
    if (i < NG) g_cnt[i] = 0.f;
    if (i == 0) { g_maxbits = 0u; g_oddOr = 0u; }
}

// ---------------- dtype detection: OR odd 32-bit words of edge_index ----------------
__global__ void k_detect(const unsigned int* __restrict__ ei32) {
    unsigned int v = 0;
    for (int i = blockIdx.x * blockDim.x + threadIdx.x; i < NE;
         i += gridDim.x * blockDim.x)
        v |= ei32[2 * i + 1];
#pragma unroll
    for (int o = 16; o; o >>= 1) v |= __shfl_xor_sync(0xffffffffu, v, o);
    if ((threadIdx.x & 31) == 0 && v) atomicOr(&g_oddOr, v);
}

// ---------------- max(edge_attr) ----------------
__global__ void k_max(const float* __restrict__ ea) {
    float m = 0.f;
    for (int i = blockIdx.x * blockDim.x + threadIdx.x; i < NE;
         i += gridDim.x * blockDim.x)
        m = fmaxf(m, ea[i]);
#pragma unroll
    for (int o = 16; o; o >>= 1) m = fmaxf(m, __shfl_xor_sync(0xffffffffu, m, o));
    __shared__ float sm[8];
    if ((threadIdx.x & 31) == 0) sm[threadIdx.x >> 5] = m;
    __syncthreads();
    if (threadIdx.x < 8) {
        m = sm[threadIdx.x];
#pragma unroll
        for (int o = 4; o; o >>= 1) m = fmaxf(m, __shfl_xor_sync(0xffu, m, o));
        if (threadIdx.x == 0) atomicMax(&g_maxbits, __float_as_uint(m));
    }
}

// ---------------- per-edge: decode indices, weighted degree + in-degree count ----------------
__global__ void k_deg(const void* __restrict__ ei, const float* __restrict__ ea) {
    int e = blockIdx.x * blockDim.x + threadIdx.x;
    if (e >= NE) return;
    int s, d;
    if (g_oddOr == 0u) {
        const long long* p = (const long long*)ei;
        s = (int)p[e]; d = (int)p[NE + e];
    } else {
        const int* p = (const int*)ei;
        s = p[e]; d = p[NE + e];
    }
    g_src[e] = s;
    g_dst[e] = d;
    float maxv = __uint_as_float(g_maxbits);
    atomicAdd(&g_deg[d], ea[e] / maxv);
    atomicAdd(&g_count[d], 1);
}

// ---------------- scan phase 1: per-block exclusive scan of counts ----------------
__global__ void k_scan1() {
    __shared__ int wsum[SCAN_BLK / 32];
    int i = blockIdx.x * SCAN_BLK + threadIdx.x;
    int c = (i < NN) ? g_count[i] : 0;
    int lane = threadIdx.x & 31, wid = threadIdx.x >> 5;
    int v = c;
#pragma unroll
    for (int o = 1; o < 32; o <<= 1) {
        int u = __shfl_up_sync(0xffffffffu, v, o);
        if (lane >= o) v += u;
    }
    if (lane == 31) wsum[wid] = v;
    __syncthreads();
    if (wid == 0) {
        int w = (lane < SCAN_BLK / 32) ? wsum[lane] : 0;
#pragma unroll
        for (int o = 1; o < SCAN_BLK / 32; o <<= 1) {
            int u = __shfl_up_sync(0xffffffffu, w, o);
            if (lane >= o) w += u;
        }
        if (lane < SCAN_BLK / 32) wsum[lane] = w;
    }
    __syncthreads();
    int excl = v - c + (wid > 0 ? wsum[wid - 1] : 0);
    if (i < NN) g_rowptr[i] = excl;
    if (threadIdx.x == SCAN_BLK - 1) g_blocksum[blockIdx.x] = excl + c;
}

// ---------------- scan phase 2: single-block exclusive scan of block sums ----------------
__global__ void k_scan2() {
    __shared__ int wsum[SCAN_BLK / 32];
    int i = threadIdx.x;
    int c = (i < NBLK) ? g_blocksum[i] : 0;
    int lane = i & 31, wid = i >> 5;
    int v = c;
#pragma unroll
    for (int o = 1; o < 32; o <<= 1) {
        int u = __shfl_up_sync(0xffffffffu, v, o);
        if (lane >= o) v += u;
    }
    if (lane == 31) wsum[wid] = v;
    __syncthreads();
    if (wid == 0) {
        int w = (lane < SCAN_BLK / 32) ? wsum[lane] : 0;
#pragma unroll
        for (int o = 1; o < SCAN_BLK / 32; o <<= 1) {
            int u = __shfl_up_sync(0xffffffffu, w, o);
            if (lane >= o) w += u;
        }
        if (lane < SCAN_BLK / 32) wsum[lane] = w;
    }
    __syncthreads();
    int excl = v - c + (wid > 0 ? wsum[wid - 1] : 0);
    if (i < NBLK) g_blocksum[i] = excl;
    if (i == 0) g_rowptr[NN] = NE;
}

// ---------------- scan phase 3: add block offsets; node factors ----------------
__global__ void k_scan3() {
    int i = blockIdx.x * SCAN_BLK + threadIdx.x;
    if (i >= NN) return;
    g_rowptr[i] += g_blocksum[blockIdx.x];
    float d = g_deg[i] + 1.f;
    g_dinv[i] = rsqrtf(d);
    g_invdeg[i] = 1.f / d;
}

// ---------------- fill CSR: norm + bucket placement ----------------
__global__ void k_fill(const float* __restrict__ ea) {
    int e = blockIdx.x * blockDim.x + threadIdx.x;
    if (e >= NE) return;
    int s = g_src[e], d = g_dst[e];
    float maxv = __uint_as_float(g_maxbits);
    float w = ea[e] / maxv;
    float norm = g_dinv[s] * w * g_dinv[d];
    int pos = g_rowptr[d] + atomicAdd(&g_fill[d], 1);
    g_csrc[pos] = s;
    g_cnorm[pos] = norm;
}

// ---------------- tiled fp32 GEMM with fused epilogue ----------------
// H = act(A) @ W ;  AGG(seed) = H * invdeg[row] + bias[col]
__global__ void k_gemm(const float* __restrict__ Aext, int ainIdx,
                       const float* __restrict__ W, const float* __restrict__ bias,
                       int aggIdx, int M, int K, int N, int reluIn) {
    __shared__ float As[64][17];
    __shared__ float Bs[16][65];
    const float* A = (ainIdx < 0) ? Aext : bufptr(ainIdx);
    float* H = g_h;
    float* AGG = bufptr(aggIdx);

    int tid = threadIdx.x;
    int tx = tid & 15, ty = tid >> 4;
    int rowBase = blockIdx.y * 64;
    int colBase = blockIdx.x * 64;

    float acc[4][4];
#pragma unroll
    for (int i = 0; i < 4; i++)
#pragma unroll
        for (int j = 0; j < 4; j++) acc[i][j] = 0.f;

    int la_r = tid >> 2;
    int la_c = (tid & 3) * 4;
    int lb_r = tid >> 4;
    int lb_c = (tid & 15) * 4;

    for (int kt = 0; kt < K; kt += 16) {
        int ar = rowBase + la_r;
        float4 va = make_float4(0.f, 0.f, 0.f, 0.f);
        if (ar < M)
            va = *(const float4*)(A + (size_t)ar * K + kt + la_c);
        if (reluIn) {
            va.x = fmaxf(va.x, 0.f); va.y = fmaxf(va.y, 0.f);
            va.z = fmaxf(va.z, 0.f); va.w = fmaxf(va.w, 0.f);
        }
        As[la_r][la_c + 0] = va.x; As[la_r][la_c + 1] = va.y;
        As[la_r][la_c + 2] = va.z; As[la_r][la_c + 3] = va.w;

        int bc = colBase + lb_c;
        float4 vb = make_float4(0.f, 0.f, 0.f, 0.f);
        if (bc < N)
            vb = *(const float4*)(W + (size_t)(kt + lb_r) * N + bc);
        Bs[lb_r][lb_c + 0] = vb.x; Bs[lb_r][lb_c + 1] = vb.y;
        Bs[lb_r][lb_c + 2] = vb.z; Bs[lb_r][lb_c + 3] = vb.w;

        __syncthreads();
#pragma unroll
        for (int kk = 0; kk < 16; kk++) {
            float a[4], b[4];
#pragma unroll
            for (int i = 0; i < 4; i++) a[i] = As[ty * 4 + i][kk];
#pragma unroll
            for (int j = 0; j < 4; j++) b[j] = Bs[kk][tx * 4 + j];
#pragma unroll
            for (int i = 0; i < 4; i++)
#pragma unroll
                for (int j = 0; j < 4; j++) acc[i][j] = fmaf(a[i], b[j], acc[i][j]);
        }
        __syncthreads();
    }

#pragma unroll
    for (int i = 0; i < 4; i++) {
        int r = rowBase + ty * 4 + i;
        if (r >= M) continue;
        float id = g_invdeg[r];
#pragma unroll
        for (int j = 0; j < 4; j++) {
            int c = colBase + tx * 4 + j;
            if (c >= N) continue;
            float h = acc[i][j];
            H[(size_t)r * N + c] = h;
            AGG[(size_t)r * N + c] = fmaf(h, id, bias[c]);
        }
    }
}

// ---------------- gather: AGG[n] += sum_{e in CSR(n)} norm * H[src] ----------------
// One thread per (node, float4-lane). No atomics.
template <int VEC, int SHIFT>
__global__ void k_gather(int aggIdx) {
    int t = blockIdx.x * blockDim.x + threadIdx.x;
    if (t >= NN * VEC) return;
    int n = t >> SHIFT;
    int j = t & (VEC - 1);
    int beg = g_rowptr[n];
    int end = g_rowptr[n + 1];
    const float4* __restrict__ H4 = (const float4*)g_h;
    float4* AGG4 = (float4*)bufptr(aggIdx);
    float4 acc = AGG4[(size_t)n * VEC + j];
    for (int k = beg; k < end; k++) {
        int s = g_csrc[k];
        float nm = g_cnorm[k];
        float4 v = H4[(size_t)s * VEC + j];
        acc.x = fmaf(nm, v.x, acc.x);
        acc.y = fmaf(nm, v.y, acc.y);
        acc.z = fmaf(nm, v.z, acc.z);
        acc.w = fmaf(nm, v.w, acc.w);
    }
    AGG4[(size_t)n * VEC + j] = acc;
}

// ---------------- pooling: relu then segment-sum ----------------
__global__ void k_pool(int aggIdx, const void* __restrict__ batch) {
    int t = blockIdx.x * blockDim.x + threadIdx.x;
    if (t >= NN * 8) return;
    int n = t >> 3, j = t & 7;
    int g;
    if (g_oddOr == 0u) g = (int)((const long long*)batch)[n];
    else               g = ((const int*)batch)[n];
    const float4* A4 = (const float4*)bufptr(aggIdx);
    float4 v = A4[(size_t)n * 8 + j];
    float* p = &g_pool[g * 32 + j * 4];
    atomicAdd(p + 0, fmaxf(v.x, 0.f));
    atomicAdd(p + 1, fmaxf(v.y, 0.f));
    atomicAdd(p + 2, fmaxf(v.z, 0.f));
    atomicAdd(p + 3, fmaxf(v.w, 0.f));
    if (j == 0) atomicAdd(&g_cnt[g], 1.f);
}

// ---------------- head ----------------
__global__ void k_out(const float* __restrict__ Wl, const float* __restrict__ bl,
                      float* __restrict__ out) {
    __shared__ float pooled[32];
    int g = blockIdx.x;
    if (threadIdx.x < 32) {
        float c = g_cnt[g];
        pooled[threadIdx.x] = g_pool[g * 32 + threadIdx.x] / fmaxf(c, 1.f);
    }
    __syncthreads();
    int o = threadIdx.x;  // 768 threads
    float acc = bl[o];
#pragma unroll
    for (int c = 0; c < 32; c++) acc = fmaf(pooled[c], Wl[c * 768 + o], acc);
    out[(size_t)g * 768 + o] = acc;
}

// ---------------- launch ----------------
extern "C" void kernel_launch(void* const* d_in, const int* in_sizes, int n_in,
                              void* d_out, int out_size) {
    const float* x = (const float*)d_in[0];
    const void* ei = d_in[1];
    const float* ea = (const float*)d_in[2];
    const void* batch = d_in[3];
    const float* W1 = (const float*)d_in[4];
    const float* b1 = (const float*)d_in[5];
    const float* W2 = (const float*)d_in[6];
    const float* b2 = (const float*)d_in[7];
    const float* W3 = (const float*)d_in[8];
    const float* b3 = (const float*)d_in[9];
    const float* Wl = (const float*)d_in[10];
    const float* bl = (const float*)d_in[11];
    float* out = (float*)d_out;

    k_init<<<(NN + 255) / 256, 256>>>();
    k_detect<<<256, 256>>>((const unsigned int*)ei);
    k_max<<<512, 256>>>(ea);
    k_deg<<<(NE + 255) / 256, 256>>>(ei, ea);
    k_scan1<<<NBLK, SCAN_BLK>>>();
    k_scan2<<<1, SCAN_BLK>>>();
    k_scan3<<<NBLK, SCAN_BLK>>>();
    k_fill<<<(NE + 255) / 256, 256>>>(ea);

    // Layer 1: x[50000,128] @ W1[128,128]; agg -> bufA(0)
    {
        dim3 grid(2, (NN + 63) / 64);
        k_gemm<<<grid, 256>>>(x, -1, W1, b1, /*agg=*/0, NN, 128, 128, /*relu=*/0);
        k_gather<32, 5><<<(NN * 32 + 255) / 256, 256>>>(/*agg=*/0);
    }
    // Layer 2: relu(bufA)[50000,128] @ W2[128,64]; agg -> bufB(1)
    {
        dim3 grid(1, (NN + 63) / 64);
        k_gemm<<<grid, 256>>>(nullptr, 0, W2, b2, /*agg=*/1, NN, 128, 64, /*relu=*/1);
        k_gather<16, 4><<<(NN * 16 + 255) / 256, 256>>>(/*agg=*/1);
    }
    // Layer 3: relu(bufB)[50000,64] @ W3[64,32]; agg -> bufA(0)
    {
        dim3 grid(1, (NN + 63) / 64);
        k_gemm<<<grid, 256>>>(nullptr, 1, W3, b3, /*agg=*/0, NN, 64, 32, /*relu=*/1);
        k_gather<8, 3><<<(NN * 8 + 255) / 256, 256>>>(/*agg=*/0);
    }
    // Pool (relu fused) + head
    k_pool<<<(NN * 8 + 255) / 256, 256>>>(/*agg=*/0, batch);
    k_out<<<NG, 768>>>(Wl, bl, out);
}

// round 5
// speedup vs baseline: 2.1341x; 1.1221x over previous
#include <cuda_runtime.h>
#include <cstdint>

#define NN 50000
#define NE 800000
#define NG 64
#define MAXF 128
#define SCAN_BLK 256
#define NBLK ((NN + SCAN_BLK - 1) / SCAN_BLK)   // 196

typedef unsigned long long ull;

// ---------------- scratch (device globals; no runtime allocation) ----------------
__device__ __align__(16) float g_bufA[NN * MAXF];
__device__ __align__(16) float g_h[NN * MAXF];
__device__ int   g_src[NE];
__device__ int   g_dst[NE];
__device__ float g_w[NE];        // normalized edge weight ea/max
__device__ int   g_csrc[NE];     // CSR-permuted src
__device__ float g_cnorm[NE];    // CSR-permuted norm
__device__ int   g_count[NN];    // in-degree
__device__ int   g_rowptr[NN + 1];
__device__ int   g_fill[NN];
__device__ int   g_blocksum[NBLK + 1];
__device__ float g_deg[NN];
__device__ float g_dinv[NN];
__device__ float g_invdeg[NN];
__device__ __align__(16) float g_pool[NG * 32];
__device__ float g_cnt[NG];
__device__ unsigned int g_maxbits;
__device__ unsigned int g_oddOr;   // 0 -> edge_index/batch are int64, else int32

// ---------------- packed f32x2 helpers ----------------
__device__ __forceinline__ ull pack2(float x, float y) {
    ull r; asm("mov.b64 %0, {%1,%2};" : "=l"(r) : "f"(x), "f"(y)); return r;
}
__device__ __forceinline__ void unpack2(ull v, float& x, float& y) {
    asm("mov.b64 {%0,%1}, %2;" : "=f"(x), "=f"(y) : "l"(v));
}
__device__ __forceinline__ void ffma2(ull& c, ull a, ull b) {
    asm("fma.rn.f32x2 %0, %1, %2, %0;" : "+l"(c) : "l"(a), "l"(b));
}

// ---------------- init ----------------
__global__ void k_init() {
    int i = blockIdx.x * blockDim.x + threadIdx.x;
    if (i < NN) { g_deg[i] = 0.f; g_count[i] = 0; g_fill[i] = 0; }
    if (i < NG * 32) g_pool[i] = 0.f;
    if (i < NG) g_cnt[i] = 0.f;
    if (i == 0) { g_maxbits = 0u; g_oddOr = 0u; }
}

// ---------------- fused dtype detection + max(edge_attr) ----------------
__global__ void k_prep(const unsigned int* __restrict__ ei32,
                       const float* __restrict__ ea) {
    unsigned int v = 0;
    float m = 0.f;
    for (int i = blockIdx.x * blockDim.x + threadIdx.x; i < NE;
         i += gridDim.x * blockDim.x) {
        v |= ei32[2 * i + 1];
        m = fmaxf(m, ea[i]);
    }
#pragma unroll
    for (int o = 16; o; o >>= 1) {
        v |= __shfl_xor_sync(0xffffffffu, v, o);
        m = fmaxf(m, __shfl_xor_sync(0xffffffffu, m, o));
    }
    if ((threadIdx.x & 31) == 0) {
        if (v) atomicOr(&g_oddOr, v);
        atomicMax(&g_maxbits, __float_as_uint(m));
    }
}

// ---------------- per-edge: decode indices, w, weighted degree + count ----------------
__global__ void k_deg(const void* __restrict__ ei, const float* __restrict__ ea) {
    int e = blockIdx.x * blockDim.x + threadIdx.x;
    if (e >= NE) return;
    int s, d;
    if (g_oddOr == 0u) {
        const long long* p = (const long long*)ei;
        s = (int)p[e]; d = (int)p[NE + e];
    } else {
        const int* p = (const int*)ei;
        s = p[e]; d = p[NE + e];
    }
    g_src[e] = s;
    g_dst[e] = d;
    float w = ea[e] / __uint_as_float(g_maxbits);
    g_w[e] = w;
    atomicAdd(&g_deg[d], w);
    atomicAdd(&g_count[d], 1);
}

// ---------------- scan phase 1 ----------------
__global__ void k_scan1() {
    __shared__ int wsum[SCAN_BLK / 32];
    int i = blockIdx.x * SCAN_BLK + threadIdx.x;
    int c = (i < NN) ? g_count[i] : 0;
    int lane = threadIdx.x & 31, wid = threadIdx.x >> 5;
    int v = c;
#pragma unroll
    for (int o = 1; o < 32; o <<= 1) {
        int u = __shfl_up_sync(0xffffffffu, v, o);
        if (lane >= o) v += u;
    }
    if (lane == 31) wsum[wid] = v;
    __syncthreads();
    if (wid == 0) {
        int w = (lane < SCAN_BLK / 32) ? wsum[lane] : 0;
#pragma unroll
        for (int o = 1; o < SCAN_BLK / 32; o <<= 1) {
            int u = __shfl_up_sync(0xffffffffu, w, o);
            if (lane >= o) w += u;
        }
        if (lane < SCAN_BLK / 32) wsum[lane] = w;
    }
    __syncthreads();
    int excl = v - c + (wid > 0 ? wsum[wid - 1] : 0);
    if (i < NN) g_rowptr[i] = excl;
    if (threadIdx.x == SCAN_BLK - 1) g_blocksum[blockIdx.x] = excl + c;
}

// ---------------- scan phase 2 ----------------
__global__ void k_scan2() {
    __shared__ int wsum[SCAN_BLK / 32];
    int i = threadIdx.x;
    int c = (i < NBLK) ? g_blocksum[i] : 0;
    int lane = i & 31, wid = i >> 5;
    int v = c;
#pragma unroll
    for (int o = 1; o < 32; o <<= 1) {
        int u = __shfl_up_sync(0xffffffffu, v, o);
        if (lane >= o) v += u;
    }
    if (lane == 31) wsum[wid] = v;
    __syncthreads();
    if (wid == 0) {
        int w = (lane < SCAN_BLK / 32) ? wsum[lane] : 0;
#pragma unroll
        for (int o = 1; o < SCAN_BLK / 32; o <<= 1) {
            int u = __shfl_up_sync(0xffffffffu, w, o);
            if (lane >= o) w += u;
        }
        if (lane < SCAN_BLK / 32) wsum[lane] = w;
    }
    __syncthreads();
    int excl = v - c + (wid > 0 ? wsum[wid - 1] : 0);
    if (i < NBLK) g_blocksum[i] = excl;
    if (i == 0) g_rowptr[NN] = NE;
}

// ---------------- scan phase 3: block offsets + node factors ----------------
__global__ void k_scan3() {
    int i = blockIdx.x * SCAN_BLK + threadIdx.x;
    if (i >= NN) return;
    g_rowptr[i] += g_blocksum[blockIdx.x];
    float d = g_deg[i] + 1.f;
    g_dinv[i] = rsqrtf(d);
    g_invdeg[i] = 1.f / d;
}

// ---------------- fill CSR ----------------
__global__ void k_fill() {
    int e = blockIdx.x * blockDim.x + threadIdx.x;
    if (e >= NE) return;
    int s = g_src[e], d = g_dst[e];
    float norm = g_dinv[s] * g_w[e] * g_dinv[d];
    int pos = g_rowptr[d] + atomicAdd(&g_fill[d], 1);
    g_csrc[pos] = s;
    g_cnorm[pos] = norm;
}

// ---------------- tiled fp32 GEMM (packed f32x2 FMA), writes H only ----------------
// H = act(A) @ W
__global__ void k_gemm(const float* __restrict__ Aext, int useBufA,
                       const float* __restrict__ W,
                       int M, int K, int N, int reluIn) {
    __shared__ float As[64][17];
    __shared__ float Bs[16][66];   // 66 keeps Bs[kk][tx*4] 8B-aligned
    const float* A = useBufA ? g_bufA : Aext;
    float* H = g_h;

    int tid = threadIdx.x;
    int tx = tid & 15, ty = tid >> 4;
    int rowBase = blockIdx.y * 64;
    int colBase = blockIdx.x * 64;

    ull acc2[4][2];
#pragma unroll
    for (int i = 0; i < 4; i++) { acc2[i][0] = 0ull; acc2[i][1] = 0ull; }

    int la_r = tid >> 2;
    int la_c = (tid & 3) * 4;
    int lb_r = tid >> 4;
    int lb_c = (tid & 15) * 4;

    for (int kt = 0; kt < K; kt += 16) {
        int ar = rowBase + la_r;
        float4 va = make_float4(0.f, 0.f, 0.f, 0.f);
        if (ar < M)
            va = *(const float4*)(A + (size_t)ar * K + kt + la_c);
        if (reluIn) {
            va.x = fmaxf(va.x, 0.f); va.y = fmaxf(va.y, 0.f);
            va.z = fmaxf(va.z, 0.f); va.w = fmaxf(va.w, 0.f);
        }
        As[la_r][la_c + 0] = va.x; As[la_r][la_c + 1] = va.y;
        As[la_r][la_c + 2] = va.z; As[la_r][la_c + 3] = va.w;

        int bc = colBase + lb_c;
        float4 vb = make_float4(0.f, 0.f, 0.f, 0.f);
        if (bc < N)
            vb = *(const float4*)(W + (size_t)(kt + lb_r) * N + bc);
        Bs[lb_r][lb_c + 0] = vb.x; Bs[lb_r][lb_c + 1] = vb.y;
        Bs[lb_r][lb_c + 2] = vb.z; Bs[lb_r][lb_c + 3] = vb.w;

        __syncthreads();
#pragma unroll
        for (int kk = 0; kk < 16; kk++) {
            ull b01 = *(const ull*)&Bs[kk][tx * 4];
            ull b23 = *(const ull*)&Bs[kk][tx * 4 + 2];
#pragma unroll
            for (int i = 0; i < 4; i++) {
                float av = As[ty * 4 + i][kk];
                ull aa = pack2(av, av);
                ffma2(acc2[i][0], aa, b01);
                ffma2(acc2[i][1], aa, b23);
            }
        }
        __syncthreads();
    }

    int c0 = colBase + tx * 4;
    if (c0 < N) {
#pragma unroll
        for (int i = 0; i < 4; i++) {
            int r = rowBase + ty * 4 + i;
            if (r >= M) continue;
            float4 o;
            unpack2(acc2[i][0], o.x, o.y);
            unpack2(acc2[i][1], o.z, o.w);
            *(float4*)(H + (size_t)r * N + c0) = o;
        }
    }
}

// ---------------- gather: AGG[n] = H[n]*invdeg + bias + sum norm*H[src] ----------------
template <int VEC, int SHIFT>
__global__ void k_gather(const float* __restrict__ bias) {
    int t = blockIdx.x * blockDim.x + threadIdx.x;
    if (t >= NN * VEC) return;
    int n = t >> SHIFT;
    int j = t & (VEC - 1);
    int beg = g_rowptr[n];
    int end = g_rowptr[n + 1];
    const float4* __restrict__ H4 = (const float4*)g_h;
    float4* AGG4 = (float4*)g_bufA;

    float id = g_invdeg[n];
    float4 b = *(const float4*)(bias + j * 4);
    float4 hv = H4[(size_t)n * VEC + j];
    float4 acc;
    acc.x = fmaf(hv.x, id, b.x);
    acc.y = fmaf(hv.y, id, b.y);
    acc.z = fmaf(hv.z, id, b.z);
    acc.w = fmaf(hv.w, id, b.w);

    for (int k = beg; k < end; k++) {
        int s = g_csrc[k];
        float nm = g_cnorm[k];
        float4 v = H4[(size_t)s * VEC + j];
        acc.x = fmaf(nm, v.x, acc.x);
        acc.y = fmaf(nm, v.y, acc.y);
        acc.z = fmaf(nm, v.z, acc.z);
        acc.w = fmaf(nm, v.w, acc.w);
    }
    AGG4[(size_t)n * VEC + j] = acc;
}

// ---------------- layer-3 gather fused with relu + mean-pool accumulation ----------------
__global__ void k_gather_pool(const float* __restrict__ bias,
                              const void* __restrict__ batch) {
    int t = blockIdx.x * blockDim.x + threadIdx.x;
    if (t >= NN * 8) return;
    int n = t >> 3;
    int j = t & 7;
    int beg = g_rowptr[n];
    int end = g_rowptr[n + 1];
    const float4* __restrict__ H4 = (const float4*)g_h;

    float id = g_invdeg[n];
    float4 b = *(const float4*)(bias + j * 4);
    float4 hv = H4[(size_t)n * 8 + j];
    float4 acc;
    acc.x = fmaf(hv.x, id, b.x);
    acc.y = fmaf(hv.y, id, b.y);
    acc.z = fmaf(hv.z, id, b.z);
    acc.w = fmaf(hv.w, id, b.w);

    for (int k = beg; k < end; k++) {
        int s = g_csrc[k];
        float nm = g_cnorm[k];
        float4 v = H4[(size_t)s * 8 + j];
        acc.x = fmaf(nm, v.x, acc.x);
        acc.y = fmaf(nm, v.y, acc.y);
        acc.z = fmaf(nm, v.z, acc.z);
        acc.w = fmaf(nm, v.w, acc.w);
    }

    int g;
    if (g_oddOr == 0u) g = (int)((const long long*)batch)[n];
    else               g = ((const int*)batch)[n];
    float* p = &g_pool[g * 32 + j * 4];
    atomicAdd(p + 0, fmaxf(acc.x, 0.f));
    atomicAdd(p + 1, fmaxf(acc.y, 0.f));
    atomicAdd(p + 2, fmaxf(acc.z, 0.f));
    atomicAdd(p + 3, fmaxf(acc.w, 0.f));
    if (j == 0) atomicAdd(&g_cnt[g], 1.f);
}

// ---------------- head ----------------
__global__ void k_out(const float* __restrict__ Wl, const float* __restrict__ bl,
                      float* __restrict__ out) {
    __shared__ float pooled[32];
    int g = blockIdx.x;
    if (threadIdx.x < 32) {
        float c = g_cnt[g];
        pooled[threadIdx.x] = g_pool[g * 32 + threadIdx.x] / fmaxf(c, 1.f);
    }
    __syncthreads();
    int o = threadIdx.x;  // 768 threads
    float acc = bl[o];
#pragma unroll
    for (int c = 0; c < 32; c++) acc = fmaf(pooled[c], Wl[c * 768 + o], acc);
    out[(size_t)g * 768 + o] = acc;
}

// ---------------- launch ----------------
extern "C" void kernel_launch(void* const* d_in, const int* in_sizes, int n_in,
                              void* d_out, int out_size) {
    const float* x = (const float*)d_in[0];
    const void* ei = d_in[1];
    const float* ea = (const float*)d_in[2];
    const void* batch = d_in[3];
    const float* W1 = (const float*)d_in[4];
    const float* b1 = (const float*)d_in[5];
    const float* W2 = (const float*)d_in[6];
    const float* b2 = (const float*)d_in[7];
    const float* W3 = (const float*)d_in[8];
    const float* b3 = (const float*)d_in[9];
    const float* Wl = (const float*)d_in[10];
    const float* bl = (const float*)d_in[11];
    float* out = (float*)d_out;

    k_init<<<(NN + 255) / 256, 256>>>();
    k_prep<<<512, 256>>>((const unsigned int*)ei, ea);
    k_deg<<<(NE + 255) / 256, 256>>>(ei, ea);
    k_scan1<<<NBLK, SCAN_BLK>>>();
    k_scan2<<<1, SCAN_BLK>>>();
    k_scan3<<<NBLK, SCAN_BLK>>>();
    k_fill<<<(NE + 255) / 256, 256>>>();

    // Layer 1: x[50000,128] @ W1[128,128] -> H; gather -> bufA
    {
        dim3 grid(2, (NN + 63) / 64);
        k_gemm<<<grid, 256>>>(x, 0, W1, NN, 128, 128, /*relu=*/0);
        k_gather<32, 5><<<(NN * 32 + 255) / 256, 256>>>(b1);
    }
    // Layer 2: relu(bufA)[50000,128] @ W2[128,64] -> H; gather -> bufA
    {
        dim3 grid(1, (NN + 63) / 64);
        k_gemm<<<grid, 256>>>(nullptr, 1, W2, NN, 128, 64, /*relu=*/1);
        k_gather<16, 4><<<(NN * 16 + 255) / 256, 256>>>(b2);
    }
    // Layer 3: relu(bufA)[50000,64] @ W3[64,32] -> H; gather fused with pool
    {
        dim3 grid(1, (NN + 63) / 64);
        k_gemm<<<grid, 256>>>(nullptr, 1, W3, NN, 64, 32, /*relu=*/1);
        k_gather_pool<<<(NN * 8 + 255) / 256, 256>>>(b3, batch);
    }
    k_out<<<NG, 768>>>(Wl, bl, out);
}

// round 6
// speedup vs baseline: 2.1501x; 1.0075x over previous
#include <cuda_runtime.h>
#include <cstdint>

#define NN 50000
#define NE 800000
#define NG 64
#define MAXF 128
#define SCAN_BLK 256
#define NBLK ((NN + SCAN_BLK - 1) / SCAN_BLK)   // 196

typedef unsigned long long ull;

// ---------------- scratch (device globals; no runtime allocation) ----------------
__device__ __align__(16) float g_bufA[NN * MAXF];
__device__ __align__(16) float g_h[NN * MAXF];
__device__ int   g_src[NE];
__device__ int   g_dst[NE];
__device__ int   g_csrc[NE];     // CSR-permuted src
__device__ float g_cnorm[NE];    // CSR-permuted norm
__device__ int   g_count[NN];    // in-degree
__device__ int   g_rowptr[NN + 1];
__device__ int   g_fill[NN];
__device__ int   g_blocksum[NBLK + 1];
__device__ float g_deg[NN];      // raw sum of ea per dst (scaled later)
__device__ float g_dinv[NN];
__device__ float g_invdeg[NN];
__device__ __align__(16) float g_pool[NG * 32];
__device__ float g_cnt[NG];
__device__ unsigned int g_maxbits;
__device__ unsigned int g_oddOr;   // 0 -> edge_index/batch are int64, else int32

// ---------------- packed f32x2 helpers ----------------
__device__ __forceinline__ ull pack2(float x, float y) {
    ull r; asm("mov.b64 %0, {%1,%2};" : "=l"(r) : "f"(x), "f"(y)); return r;
}
__device__ __forceinline__ void unpack2(ull v, float& x, float& y) {
    asm("mov.b64 {%0,%1}, %2;" : "=f"(x), "=f"(y) : "l"(v));
}
__device__ __forceinline__ void ffma2(ull& c, ull a, ull b) {
    asm("fma.rn.f32x2 %0, %1, %2, %0;" : "+l"(c) : "l"(a), "l"(b));
}

// ---------------- init + fast dtype detection ----------------
// int64 data (values < 2^31): odd 32-bit words are zero high-halves.
// int32 data: odd words are node indices; 8192 consecutive all-zero has
// probability ~(1/50000)^8192 ~ 0, so a prefix scan is conclusive.
__global__ void k_init(const unsigned int* __restrict__ ei32) {
    int i = blockIdx.x * blockDim.x + threadIdx.x;
    if (i < NN) { g_deg[i] = 0.f; g_count[i] = 0; g_fill[i] = 0; }
    if (i < NG * 32) g_pool[i] = 0.f;
    if (i < NG) g_cnt[i] = 0.f;
    if (i == 0) { g_maxbits = 0u; g_oddOr = 0u; }
    if (blockIdx.x == 0) {
        __syncthreads();
        unsigned int v = 0;
        for (int t = threadIdx.x; t < 8192; t += blockDim.x)
            v |= ei32[2 * t + 1];
#pragma unroll
        for (int o = 16; o; o >>= 1) v |= __shfl_xor_sync(0xffffffffu, v, o);
        if ((threadIdx.x & 31) == 0 && v) atomicOr(&g_oddOr, v);
    }
}

// ---------------- fused per-edge pass: decode, max(ea), raw deg, count ----------------
__global__ void k_prep(const void* __restrict__ ei, const float* __restrict__ ea) {
    bool is64 = (g_oddOr == 0u);
    const long long* p64 = (const long long*)ei;
    const int* p32 = (const int*)ei;
    float m = 0.f;
    for (int e = blockIdx.x * blockDim.x + threadIdx.x; e < NE;
         e += gridDim.x * blockDim.x) {
        int s, d;
        if (is64) { s = (int)p64[e]; d = (int)p64[NE + e]; }
        else      { s = p32[e];      d = p32[NE + e]; }
        g_src[e] = s;
        g_dst[e] = d;
        float a = ea[e];
        m = fmaxf(m, a);
        atomicAdd(&g_deg[d], a);
        atomicAdd(&g_count[d], 1);
    }
#pragma unroll
    for (int o = 16; o; o >>= 1) m = fmaxf(m, __shfl_xor_sync(0xffffffffu, m, o));
    if ((threadIdx.x & 31) == 0) atomicMax(&g_maxbits, __float_as_uint(m));
}

// ---------------- scan phase 1 ----------------
__global__ void k_scan1() {
    __shared__ int wsum[SCAN_BLK / 32];
    int i = blockIdx.x * SCAN_BLK + threadIdx.x;
    int c = (i < NN) ? g_count[i] : 0;
    int lane = threadIdx.x & 31, wid = threadIdx.x >> 5;
    int v = c;
#pragma unroll
    for (int o = 1; o < 32; o <<= 1) {
        int u = __shfl_up_sync(0xffffffffu, v, o);
        if (lane >= o) v += u;
    }
    if (lane == 31) wsum[wid] = v;
    __syncthreads();
    if (wid == 0) {
        int w = (lane < SCAN_BLK / 32) ? wsum[lane] : 0;
#pragma unroll
        for (int o = 1; o < SCAN_BLK / 32; o <<= 1) {
            int u = __shfl_up_sync(0xffffffffu, w, o);
            if (lane >= o) w += u;
        }
        if (lane < SCAN_BLK / 32) wsum[lane] = w;
    }
    __syncthreads();
    int excl = v - c + (wid > 0 ? wsum[wid - 1] : 0);
    if (i < NN) g_rowptr[i] = excl;
    if (threadIdx.x == SCAN_BLK - 1) g_blocksum[blockIdx.x] = excl + c;
}

// ---------------- scan phase 2 ----------------
__global__ void k_scan2() {
    __shared__ int wsum[SCAN_BLK / 32];
    int i = threadIdx.x;
    int c = (i < NBLK) ? g_blocksum[i] : 0;
    int lane = i & 31, wid = i >> 5;
    int v = c;
#pragma unroll
    for (int o = 1; o < 32; o <<= 1) {
        int u = __shfl_up_sync(0xffffffffu, v, o);
        if (lane >= o) v += u;
    }
    if (lane == 31) wsum[wid] = v;
    __syncthreads();
    if (wid == 0) {
        int w = (lane < SCAN_BLK / 32) ? wsum[lane] : 0;
#pragma unroll
        for (int o = 1; o < SCAN_BLK / 32; o <<= 1) {
            int u = __shfl_up_sync(0xffffffffu, w, o);
            if (lane >= o) w += u;
        }
        if (lane < SCAN_BLK / 32) wsum[lane] = w;
    }
    __syncthreads();
    int excl = v - c + (wid > 0 ? wsum[wid - 1] : 0);
    if (i < NBLK) g_blocksum[i] = excl;
    if (i == 0) g_rowptr[NN] = NE;
}

// ---------------- scan phase 3: block offsets + node factors (deg scaled here) ----------------
__global__ void k_scan3() {
    int i = blockIdx.x * SCAN_BLK + threadIdx.x;
    if (i >= NN) return;
    g_rowptr[i] += g_blocksum[blockIdx.x];
    float invmax = 1.f / __uint_as_float(g_maxbits);
    float d = fmaf(g_deg[i], invmax, 1.f);
    g_dinv[i] = rsqrtf(d);
    g_invdeg[i] = 1.f / d;
}

// ---------------- fill CSR ----------------
__global__ void k_fill(const float* __restrict__ ea) {
    int e = blockIdx.x * blockDim.x + threadIdx.x;
    if (e >= NE) return;
    int s = g_src[e], d = g_dst[e];
    float invmax = 1.f / __uint_as_float(g_maxbits);
    float norm = g_dinv[s] * (ea[e] * invmax) * g_dinv[d];
    int pos = g_rowptr[d] + atomicAdd(&g_fill[d], 1);
    g_csrc[pos] = s;
    g_cnorm[pos] = norm;
}

// ---------------- tiled fp32 GEMM (packed f32x2 FMA), writes H only ----------------
__global__ void k_gemm(const float* __restrict__ Aext, int useBufA,
                       const float* __restrict__ W,
                       int M, int K, int N, int reluIn) {
    __shared__ float As[64][17];
    __shared__ float Bs[16][66];
    const float* A = useBufA ? g_bufA : Aext;
    float* H = g_h;

    int tid = threadIdx.x;
    int tx = tid & 15, ty = tid >> 4;
    int rowBase = blockIdx.y * 64;
    int colBase = blockIdx.x * 64;

    ull acc2[4][2];
#pragma unroll
    for (int i = 0; i < 4; i++) { acc2[i][0] = 0ull; acc2[i][1] = 0ull; }

    int la_r = tid >> 2;
    int la_c = (tid & 3) * 4;
    int lb_r = tid >> 4;
    int lb_c = (tid & 15) * 4;

    for (int kt = 0; kt < K; kt += 16) {
        int ar = rowBase + la_r;
        float4 va = make_float4(0.f, 0.f, 0.f, 0.f);
        if (ar < M)
            va = *(const float4*)(A + (size_t)ar * K + kt + la_c);
        if (reluIn) {
            va.x = fmaxf(va.x, 0.f); va.y = fmaxf(va.y, 0.f);
            va.z = fmaxf(va.z, 0.f); va.w = fmaxf(va.w, 0.f);
        }
        As[la_r][la_c + 0] = va.x; As[la_r][la_c + 1] = va.y;
        As[la_r][la_c + 2] = va.z; As[la_r][la_c + 3] = va.w;

        int bc = colBase + lb_c;
        float4 vb = make_float4(0.f, 0.f, 0.f, 0.f);
        if (bc < N)
            vb = *(const float4*)(W + (size_t)(kt + lb_r) * N + bc);
        Bs[lb_r][lb_c + 0] = vb.x; Bs[lb_r][lb_c + 1] = vb.y;
        Bs[lb_r][lb_c + 2] = vb.z; Bs[lb_r][lb_c + 3] = vb.w;

        __syncthreads();
#pragma unroll
        for (int kk = 0; kk < 16; kk++) {
            ull b01 = *(const ull*)&Bs[kk][tx * 4];
            ull b23 = *(const ull*)&Bs[kk][tx * 4 + 2];
#pragma unroll
            for (int i = 0; i < 4; i++) {
                float av = As[ty * 4 + i][kk];
                ull aa = pack2(av, av);
                ffma2(acc2[i][0], aa, b01);
                ffma2(acc2[i][1], aa, b23);
            }
        }
        __syncthreads();
    }

    int c0 = colBase + tx * 4;
    if (c0 < N) {
#pragma unroll
        for (int i = 0; i < 4; i++) {
            int r = rowBase + ty * 4 + i;
            if (r >= M) continue;
            float4 o;
            unpack2(acc2[i][0], o.x, o.y);
            unpack2(acc2[i][1], o.z, o.w);
            *(float4*)(H + (size_t)r * N + c0) = o;
        }
    }
}

// ---------------- gather (unrolled x4): AGG[n] = H[n]*invdeg + bias + sum norm*H[src] ----------------
template <int VEC, int SHIFT>
__global__ void k_gather(const float* __restrict__ bias) {
    int t = blockIdx.x * blockDim.x + threadIdx.x;
    if (t >= NN * VEC) return;
    int n = t >> SHIFT;
    int j = t & (VEC - 1);
    int beg = g_rowptr[n];
    int end = g_rowptr[n + 1];
    const float4* __restrict__ H4 = (const float4*)g_h;
    const int* __restrict__ csrc = g_csrc;
    const float* __restrict__ cnorm = g_cnorm;
    float4* AGG4 = (float4*)g_bufA;

    float id = g_invdeg[n];
    float4 b = *(const float4*)(bias + j * 4);
    float4 hv = H4[(size_t)n * VEC + j];
    float4 acc;
    acc.x = fmaf(hv.x, id, b.x);
    acc.y = fmaf(hv.y, id, b.y);
    acc.z = fmaf(hv.z, id, b.z);
    acc.w = fmaf(hv.w, id, b.w);

    int k = beg;
    for (; k + 4 <= end; k += 4) {
        int s0 = csrc[k], s1 = csrc[k + 1], s2 = csrc[k + 2], s3 = csrc[k + 3];
        float n0 = cnorm[k], n1 = cnorm[k + 1], n2 = cnorm[k + 2], n3 = cnorm[k + 3];
        float4 v0 = H4[(size_t)s0 * VEC + j];
        float4 v1 = H4[(size_t)s1 * VEC + j];
        float4 v2 = H4[(size_t)s2 * VEC + j];
        float4 v3 = H4[(size_t)s3 * VEC + j];
        acc.x = fmaf(n0, v0.x, acc.x); acc.y = fmaf(n0, v0.y, acc.y);
        acc.z = fmaf(n0, v0.z, acc.z); acc.w = fmaf(n0, v0.w, acc.w);
        acc.x = fmaf(n1, v1.x, acc.x); acc.y = fmaf(n1, v1.y, acc.y);
        acc.z = fmaf(n1, v1.z, acc.z); acc.w = fmaf(n1, v1.w, acc.w);
        acc.x = fmaf(n2, v2.x, acc.x); acc.y = fmaf(n2, v2.y, acc.y);
        acc.z = fmaf(n2, v2.z, acc.z); acc.w = fmaf(n2, v2.w, acc.w);
        acc.x = fmaf(n3, v3.x, acc.x); acc.y = fmaf(n3, v3.y, acc.y);
        acc.z = fmaf(n3, v3.z, acc.z); acc.w = fmaf(n3, v3.w, acc.w);
    }
    for (; k < end; k++) {
        int s = csrc[k];
        float nm = cnorm[k];
        float4 v = H4[(size_t)s * VEC + j];
        acc.x = fmaf(nm, v.x, acc.x);
        acc.y = fmaf(nm, v.y, acc.y);
        acc.z = fmaf(nm, v.z, acc.z);
        acc.w = fmaf(nm, v.w, acc.w);
    }
    AGG4[(size_t)n * VEC + j] = acc;
}

// ---------------- layer-3 gather fused with relu + mean-pool accumulation ----------------
__global__ void k_gather_pool(const float* __restrict__ bias,
                              const void* __restrict__ batch) {
    int t = blockIdx.x * blockDim.x + threadIdx.x;
    if (t >= NN * 8) return;
    int n = t >> 3;
    int j = t & 7;
    int beg = g_rowptr[n];
    int end = g_rowptr[n + 1];
    const float4* __restrict__ H4 = (const float4*)g_h;
    const int* __restrict__ csrc = g_csrc;
    const float* __restrict__ cnorm = g_cnorm;

    float id = g_invdeg[n];
    float4 b = *(const float4*)(bias + j * 4);
    float4 hv = H4[(size_t)n * 8 + j];
    float4 acc;
    acc.x = fmaf(hv.x, id, b.x);
    acc.y = fmaf(hv.y, id, b.y);
    acc.z = fmaf(hv.z, id, b.z);
    acc.w = fmaf(hv.w, id, b.w);

    int k = beg;
    for (; k + 4 <= end; k += 4) {
        int s0 = csrc[k], s1 = csrc[k + 1], s2 = csrc[k + 2], s3 = csrc[k + 3];
        float n0 = cnorm[k], n1 = cnorm[k + 1], n2 = cnorm[k + 2], n3 = cnorm[k + 3];
        float4 v0 = H4[(size_t)s0 * 8 + j];
        float4 v1 = H4[(size_t)s1 * 8 + j];
        float4 v2 = H4[(size_t)s2 * 8 + j];
        float4 v3 = H4[(size_t)s3 * 8 + j];
        acc.x = fmaf(n0, v0.x, acc.x); acc.y = fmaf(n0, v0.y, acc.y);
        acc.z = fmaf(n0, v0.z, acc.z); acc.w = fmaf(n0, v0.w, acc.w);
        acc.x = fmaf(n1, v1.x, acc.x); acc.y = fmaf(n1, v1.y, acc.y);
        acc.z = fmaf(n1, v1.z, acc.z); acc.w = fmaf(n1, v1.w, acc.w);
        acc.x = fmaf(n2, v2.x, acc.x); acc.y = fmaf(n2, v2.y, acc.y);
        acc.z = fmaf(n2, v2.z, acc.z); acc.w = fmaf(n2, v2.w, acc.w);
        acc.x = fmaf(n3, v3.x, acc.x); acc.y = fmaf(n3, v3.y, acc.y);
        acc.z = fmaf(n3, v3.z, acc.z); acc.w = fmaf(n3, v3.w, acc.w);
    }
    for (; k < end; k++) {
        int s = csrc[k];
        float nm = cnorm[k];
        float4 v = H4[(size_t)s * 8 + j];
        acc.x = fmaf(nm, v.x, acc.x);
        acc.y = fmaf(nm, v.y, acc.y);
        acc.z = fmaf(nm, v.z, acc.z);
        acc.w = fmaf(nm, v.w, acc.w);
    }

    int g;
    if (g_oddOr == 0u) g = (int)((const long long*)batch)[n];
    else               g = ((const int*)batch)[n];
    float* p = &g_pool[g * 32 + j * 4];
    atomicAdd(p + 0, fmaxf(acc.x, 0.f));
    atomicAdd(p + 1, fmaxf(acc.y, 0.f));
    atomicAdd(p + 2, fmaxf(acc.z, 0.f));
    atomicAdd(p + 3, fmaxf(acc.w, 0.f));
    if (j == 0) atomicAdd(&g_cnt[g], 1.f);
}

// ---------------- head ----------------
__global__ void k_out(const float* __restrict__ Wl, const float* __restrict__ bl,
                      float* __restrict__ out) {
    __shared__ float pooled[32];
    int g = blockIdx.x;
    if (threadIdx.x < 32) {
        float c = g_cnt[g];
        pooled[threadIdx.x] = g_pool[g * 32 + threadIdx.x] / fmaxf(c, 1.f);
    }
    __syncthreads();
    int o = threadIdx.x;  // 768 threads
    float acc = bl[o];
#pragma unroll
    for (int c = 0; c < 32; c++) acc = fmaf(pooled[c], Wl[c * 768 + o], acc);
    out[(size_t)g * 768 + o] = acc;
}

// ---------------- launch ----------------
extern "C" void kernel_launch(void* const* d_in, const int* in_sizes, int n_in,
                              void* d_out, int out_size) {
    const float* x = (const float*)d_in[0];
    const void* ei = d_in[1];
    const float* ea = (const float*)d_in[2];
    const void* batch = d_in[3];
    const float* W1 = (const float*)d_in[4];
    const float* b1 = (const float*)d_in[5];
    const float* W2 = (const float*)d_in[6];
    const float* b2 = (const float*)d_in[7];
    const float* W3 = (const float*)d_in[8];
    const float* b3 = (const float*)d_in[9];
    const float* Wl = (const float*)d_in[10];
    const float* bl = (const float*)d_in[11];
    float* out = (float*)d_out;

    k_init<<<(NN + 255) / 256, 256>>>((const unsigned int*)ei);
    k_prep<<<512, 256>>>(ei, ea);
    k_scan1<<<NBLK, SCAN_BLK>>>();
    k_scan2<<<1, SCAN_BLK>>>();
    k_scan3<<<NBLK, SCAN_BLK>>>();
    k_fill<<<(NE + 255) / 256, 256>>>(ea);

    // Layer 1: x[50000,128] @ W1[128,128] -> H; gather -> bufA
    {
        dim3 grid(2, (NN + 63) / 64);
        k_gemm<<<grid, 256>>>(x, 0, W1, NN, 128, 128, /*relu=*/0);
        k_gather<32, 5><<<(NN * 32 + 255) / 256, 256>>>(b1);
    }
    // Layer 2: relu(bufA)[50000,128] @ W2[128,64] -> H; gather -> bufA
    {
        dim3 grid(1, (NN + 63) / 64);
        k_gemm<<<grid, 256>>>(nullptr, 1, W2, NN, 128, 64, /*relu=*/1);
        k_gather<16, 4><<<(NN * 16 + 255) / 256, 256>>>(b2);
    }
    // Layer 3: relu(bufA)[50000,64] @ W3[64,32] -> H; gather fused with pool
    {
        dim3 grid(1, (NN + 63) / 64);
        k_gemm<<<grid, 256>>>(nullptr, 1, W3, NN, 64, 32, /*relu=*/1);
        k_gather_pool<<<(NN * 8 + 255) / 256, 256>>>(b3, batch);
    }
    k_out<<<NG, 768>>>(Wl, bl, out);
}

// round 7
// speedup vs baseline: 2.2085x; 1.0271x over previous
#include <cuda_runtime.h>
#include <cstdint>

#define NN 50000
#define NE 800000
#define NG 64
#define MAXF 128
#define SCAN_BLK 256
#define NBLK ((NN + SCAN_BLK - 1) / SCAN_BLK)   // 196

typedef unsigned long long ull;

// ---------------- scratch (device globals; no runtime allocation) ----------------
__device__ __align__(16) float g_bufA[NN * MAXF];
__device__ __align__(16) float g_h[NN * MAXF];
__device__ int   g_src[NE];
__device__ int   g_dst[NE];
__device__ int   g_csrc[NE];     // CSR-permuted src
__device__ float g_cnorm[NE];    // CSR-permuted norm
__device__ int   g_count[NN];    // in-degree
__device__ int   g_rowptr[NN + 1];
__device__ int   g_fill[NN];
__device__ int   g_blocksum[NBLK + 1];
__device__ float g_deg[NN];      // raw sum of ea per dst (scaled later)
__device__ float g_dinv[NN];
__device__ float g_invdeg[NN];
__device__ __align__(16) float g_pool[NG * 32];
__device__ float g_cnt[NG];
__device__ unsigned int g_maxbits;
__device__ unsigned int g_oddOr;   // 0 -> edge_index/batch are int64, else int32

// ---------------- packed f32x2 helpers ----------------
__device__ __forceinline__ ull pack2(float x, float y) {
    ull r; asm("mov.b64 %0, {%1,%2};" : "=l"(r) : "f"(x), "f"(y)); return r;
}
__device__ __forceinline__ void unpack2(ull v, float& x, float& y) {
    asm("mov.b64 {%0,%1}, %2;" : "=f"(x), "=f"(y) : "l"(v));
}
__device__ __forceinline__ void ffma2(ull& c, ull a, ull b) {
    asm("fma.rn.f32x2 %0, %1, %2, %0;" : "+l"(c) : "l"(a), "l"(b));
}

// ---------------- init + fast dtype detection ----------------
__global__ void k_init(const unsigned int* __restrict__ ei32) {
    int i = blockIdx.x * blockDim.x + threadIdx.x;
    if (i < NN) { g_deg[i] = 0.f; g_count[i] = 0; g_fill[i] = 0; }
    if (i < NG * 32) g_pool[i] = 0.f;
    if (i < NG) g_cnt[i] = 0.f;
    if (i == 0) { g_maxbits = 0u; g_oddOr = 0u; }
    if (blockIdx.x == 0) {
        __syncthreads();
        unsigned int v = 0;
        for (int t = threadIdx.x; t < 8192; t += blockDim.x)
            v |= ei32[2 * t + 1];
#pragma unroll
        for (int o = 16; o; o >>= 1) v |= __shfl_xor_sync(0xffffffffu, v, o);
        if ((threadIdx.x & 31) == 0 && v) atomicOr(&g_oddOr, v);
    }
}

// ---------------- fused per-edge pass: decode, max(ea), raw deg, count ----------------
__global__ void k_prep(const void* __restrict__ ei, const float* __restrict__ ea) {
    bool is64 = (g_oddOr == 0u);
    const long long* p64 = (const long long*)ei;
    const int* p32 = (const int*)ei;
    float m = 0.f;
    for (int e = blockIdx.x * blockDim.x + threadIdx.x; e < NE;
         e += gridDim.x * blockDim.x) {
        int s, d;
        if (is64) { s = (int)p64[e]; d = (int)p64[NE + e]; }
        else      { s = p32[e];      d = p32[NE + e]; }
        g_src[e] = s;
        g_dst[e] = d;
        float a = ea[e];
        m = fmaxf(m, a);
        atomicAdd(&g_deg[d], a);
        atomicAdd(&g_count[d], 1);
    }
#pragma unroll
    for (int o = 16; o; o >>= 1) m = fmaxf(m, __shfl_xor_sync(0xffffffffu, m, o));
    if ((threadIdx.x & 31) == 0) atomicMax(&g_maxbits, __float_as_uint(m));
}

// ---------------- scan phase 1 ----------------
__global__ void k_scan1() {
    __shared__ int wsum[SCAN_BLK / 32];
    int i = blockIdx.x * SCAN_BLK + threadIdx.x;
    int c = (i < NN) ? g_count[i] : 0;
    int lane = threadIdx.x & 31, wid = threadIdx.x >> 5;
    int v = c;
#pragma unroll
    for (int o = 1; o < 32; o <<= 1) {
        int u = __shfl_up_sync(0xffffffffu, v, o);
        if (lane >= o) v += u;
    }
    if (lane == 31) wsum[wid] = v;
    __syncthreads();
    if (wid == 0) {
        int w = (lane < SCAN_BLK / 32) ? wsum[lane] : 0;
#pragma unroll
        for (int o = 1; o < SCAN_BLK / 32; o <<= 1) {
            int u = __shfl_up_sync(0xffffffffu, w, o);
            if (lane >= o) w += u;
        }
        if (lane < SCAN_BLK / 32) wsum[lane] = w;
    }
    __syncthreads();
    int excl = v - c + (wid > 0 ? wsum[wid - 1] : 0);
    if (i < NN) g_rowptr[i] = excl;
    if (threadIdx.x == SCAN_BLK - 1) g_blocksum[blockIdx.x] = excl + c;
}

// ---------------- scan phase 2 ----------------
__global__ void k_scan2() {
    __shared__ int wsum[SCAN_BLK / 32];
    int i = threadIdx.x;
    int c = (i < NBLK) ? g_blocksum[i] : 0;
    int lane = i & 31, wid = i >> 5;
    int v = c;
#pragma unroll
    for (int o = 1; o < 32; o <<= 1) {
        int u = __shfl_up_sync(0xffffffffu, v, o);
        if (lane >= o) v += u;
    }
    if (lane == 31) wsum[wid] = v;
    __syncthreads();
    if (wid == 0) {
        int w = (lane < SCAN_BLK / 32) ? wsum[lane] : 0;
#pragma unroll
        for (int o = 1; o < SCAN_BLK / 32; o <<= 1) {
            int u = __shfl_up_sync(0xffffffffu, w, o);
            if (lane >= o) w += u;
        }
        if (lane < SCAN_BLK / 32) wsum[lane] = w;
    }
    __syncthreads();
    int excl = v - c + (wid > 0 ? wsum[wid - 1] : 0);
    if (i < NBLK) g_blocksum[i] = excl;
    if (i == 0) g_rowptr[NN] = NE;
}

// ---------------- scan phase 3: block offsets + node factors ----------------
__global__ void k_scan3() {
    int i = blockIdx.x * SCAN_BLK + threadIdx.x;
    if (i >= NN) return;
    g_rowptr[i] += g_blocksum[blockIdx.x];
    float invmax = 1.f / __uint_as_float(g_maxbits);
    float d = fmaf(g_deg[i], invmax, 1.f);
    g_dinv[i] = rsqrtf(d);
    g_invdeg[i] = 1.f / d;
}

// ---------------- fill CSR ----------------
__global__ void k_fill(const float* __restrict__ ea) {
    int e = blockIdx.x * blockDim.x + threadIdx.x;
    if (e >= NE) return;
    int s = g_src[e], d = g_dst[e];
    float invmax = 1.f / __uint_as_float(g_maxbits);
    float norm = g_dinv[s] * (ea[e] * invmax) * g_dinv[d];
    int pos = g_rowptr[d] + atomicAdd(&g_fill[d], 1);
    g_csrc[pos] = s;
    g_cnorm[pos] = norm;
}

// ---------------- tiled fp32 GEMM (packed f32x2 FMA), writes H only ----------------
__global__ void k_gemm(const float* __restrict__ Aext, int useBufA,
                       const float* __restrict__ W,
                       int M, int K, int N, int reluIn) {
    __shared__ float As[64][17];
    __shared__ float Bs[16][66];
    const float* A = useBufA ? g_bufA : Aext;
    float* H = g_h;

    int tid = threadIdx.x;
    int tx = tid & 15, ty = tid >> 4;
    int rowBase = blockIdx.y * 64;
    int colBase = blockIdx.x * 64;

    ull acc2[4][2];
#pragma unroll
    for (int i = 0; i < 4; i++) { acc2[i][0] = 0ull; acc2[i][1] = 0ull; }

    int la_r = tid >> 2;
    int la_c = (tid & 3) * 4;
    int lb_r = tid >> 4;
    int lb_c = (tid & 15) * 4;

    for (int kt = 0; kt < K; kt += 16) {
        int ar = rowBase + la_r;
        float4 va = make_float4(0.f, 0.f, 0.f, 0.f);
        if (ar < M)
            va = *(const float4*)(A + (size_t)ar * K + kt + la_c);
        if (reluIn) {
            va.x = fmaxf(va.x, 0.f); va.y = fmaxf(va.y, 0.f);
            va.z = fmaxf(va.z, 0.f); va.w = fmaxf(va.w, 0.f);
        }
        As[la_r][la_c + 0] = va.x; As[la_r][la_c + 1] = va.y;
        As[la_r][la_c + 2] = va.z; As[la_r][la_c + 3] = va.w;

        int bc = colBase + lb_c;
        float4 vb = make_float4(0.f, 0.f, 0.f, 0.f);
        if (bc < N)
            vb = *(const float4*)(W + (size_t)(kt + lb_r) * N + bc);
        Bs[lb_r][lb_c + 0] = vb.x; Bs[lb_r][lb_c + 1] = vb.y;
        Bs[lb_r][lb_c + 2] = vb.z; Bs[lb_r][lb_c + 3] = vb.w;

        __syncthreads();
#pragma unroll
        for (int kk = 0; kk < 16; kk++) {
            ull b01 = *(const ull*)&Bs[kk][tx * 4];
            ull b23 = *(const ull*)&Bs[kk][tx * 4 + 2];
#pragma unroll
            for (int i = 0; i < 4; i++) {
                float av = As[ty * 4 + i][kk];
                ull aa = pack2(av, av);
                ffma2(acc2[i][0], aa, b01);
                ffma2(acc2[i][1], aa, b23);
            }
        }
        __syncthreads();
    }

    int c0 = colBase + tx * 4;
    if (c0 < N) {
#pragma unroll
        for (int i = 0; i < 4; i++) {
            int r = rowBase + ty * 4 + i;
            if (r >= M) continue;
            float4 o;
            unpack2(acc2[i][0], o.x, o.y);
            unpack2(acc2[i][1], o.z, o.w);
            *(float4*)(H + (size_t)r * N + c0) = o;
        }
    }
}

// ---------------- gather (unrolled x4): AGG[n] = H[n]*invdeg + bias + sum norm*H[src] ----------------
template <int VEC, int SHIFT>
__global__ void k_gather(const float* __restrict__ bias) {
    int t = blockIdx.x * blockDim.x + threadIdx.x;
    if (t >= NN * VEC) return;
    int n = t >> SHIFT;
    int j = t & (VEC - 1);
    int beg = g_rowptr[n];
    int end = g_rowptr[n + 1];
    const float4* __restrict__ H4 = (const float4*)g_h;
    const int* __restrict__ csrc = g_csrc;
    const float* __restrict__ cnorm = g_cnorm;
    float4* AGG4 = (float4*)g_bufA;

    float id = g_invdeg[n];
    float4 b = *(const float4*)(bias + j * 4);
    float4 hv = H4[(size_t)n * VEC + j];
    float4 acc;
    acc.x = fmaf(hv.x, id, b.x);
    acc.y = fmaf(hv.y, id, b.y);
    acc.z = fmaf(hv.z, id, b.z);
    acc.w = fmaf(hv.w, id, b.w);

    int k = beg;
    for (; k + 4 <= end; k += 4) {
        int s0 = csrc[k], s1 = csrc[k + 1], s2 = csrc[k + 2], s3 = csrc[k + 3];
        float n0 = cnorm[k], n1 = cnorm[k + 1], n2 = cnorm[k + 2], n3 = cnorm[k + 3];
        float4 v0 = H4[(size_t)s0 * VEC + j];
        float4 v1 = H4[(size_t)s1 * VEC + j];
        float4 v2 = H4[(size_t)s2 * VEC + j];
        float4 v3 = H4[(size_t)s3 * VEC + j];
        acc.x = fmaf(n0, v0.x, acc.x); acc.y = fmaf(n0, v0.y, acc.y);
        acc.z = fmaf(n0, v0.z, acc.z); acc.w = fmaf(n0, v0.w, acc.w);
        acc.x = fmaf(n1, v1.x, acc.x); acc.y = fmaf(n1, v1.y, acc.y);
        acc.z = fmaf(n1, v1.z, acc.z); acc.w = fmaf(n1, v1.w, acc.w);
        acc.x = fmaf(n2, v2.x, acc.x); acc.y = fmaf(n2, v2.y, acc.y);
        acc.z = fmaf(n2, v2.z, acc.z); acc.w = fmaf(n2, v2.w, acc.w);
        acc.x = fmaf(n3, v3.x, acc.x); acc.y = fmaf(n3, v3.y, acc.y);
        acc.z = fmaf(n3, v3.z, acc.z); acc.w = fmaf(n3, v3.w, acc.w);
    }
    for (; k < end; k++) {
        int s = csrc[k];
        float nm = cnorm[k];
        float4 v = H4[(size_t)s * VEC + j];
        acc.x = fmaf(nm, v.x, acc.x);
        acc.y = fmaf(nm, v.y, acc.y);
        acc.z = fmaf(nm, v.z, acc.z);
        acc.w = fmaf(nm, v.w, acc.w);
    }
    AGG4[(size_t)n * VEC + j] = acc;
}

// ---------------- layer-3 gather fused with relu + mean-pool accumulation ----------------
__global__ void k_gather_pool(const float* __restrict__ bias,
                              const void* __restrict__ batch) {
    int t = blockIdx.x * blockDim.x + threadIdx.x;
    if (t >= NN * 8) return;
    int n = t >> 3;
    int j = t & 7;
    int beg = g_rowptr[n];
    int end = g_rowptr[n + 1];
    const float4* __restrict__ H4 = (const float4*)g_h;
    const int* __restrict__ csrc = g_csrc;
    const float* __restrict__ cnorm = g_cnorm;

    float id = g_invdeg[n];
    float4 b = *(const float4*)(bias + j * 4);
    float4 hv = H4[(size_t)n * 8 + j];
    float4 acc;
    acc.x = fmaf(hv.x, id, b.x);
    acc.y = fmaf(hv.y, id, b.y);
    acc.z = fmaf(hv.z, id, b.z);
    acc.w = fmaf(hv.w, id, b.w);

    int k = beg;
    for (; k + 4 <= end; k += 4) {
        int s0 = csrc[k], s1 = csrc[k + 1], s2 = csrc[k + 2], s3 = csrc[k + 3];
        float n0 = cnorm[k], n1 = cnorm[k + 1], n2 = cnorm[k + 2], n3 = cnorm[k + 3];
        float4 v0 = H4[(size_t)s0 * 8 + j];
        float4 v1 = H4[(size_t)s1 * 8 + j];
        float4 v2 = H4[(size_t)s2 * 8 + j];
        float4 v3 = H4[(size_t)s3 * 8 + j];
        acc.x = fmaf(n0, v0.x, acc.x); acc.y = fmaf(n0, v0.y, acc.y);
        acc.z = fmaf(n0, v0.z, acc.z); acc.w = fmaf(n0, v0.w, acc.w);
        acc.x = fmaf(n1, v1.x, acc.x); acc.y = fmaf(n1, v1.y, acc.y);
        acc.z = fmaf(n1, v1.z, acc.z); acc.w = fmaf(n1, v1.w, acc.w);
        acc.x = fmaf(n2, v2.x, acc.x); acc.y = fmaf(n2, v2.y, acc.y);
        acc.z = fmaf(n2, v2.z, acc.z); acc.w = fmaf(n2, v2.w, acc.w);
        acc.x = fmaf(n3, v3.x, acc.x); acc.y = fmaf(n3, v3.y, acc.y);
        acc.z = fmaf(n3, v3.z, acc.z); acc.w = fmaf(n3, v3.w, acc.w);
    }
    for (; k < end; k++) {
        int s = csrc[k];
        float nm = cnorm[k];
        float4 v = H4[(size_t)s * 8 + j];
        acc.x = fmaf(nm, v.x, acc.x);
        acc.y = fmaf(nm, v.y, acc.y);
        acc.z = fmaf(nm, v.z, acc.z);
        acc.w = fmaf(nm, v.w, acc.w);
    }

    int g;
    if (g_oddOr == 0u) g = (int)((const long long*)batch)[n];
    else               g = ((const int*)batch)[n];
    float* p = &g_pool[g * 32 + j * 4];
    atomicAdd(p + 0, fmaxf(acc.x, 0.f));
    atomicAdd(p + 1, fmaxf(acc.y, 0.f));
    atomicAdd(p + 2, fmaxf(acc.z, 0.f));
    atomicAdd(p + 3, fmaxf(acc.w, 0.f));
    if (j == 0) atomicAdd(&g_cnt[g], 1.f);
}

// ---------------- head ----------------
__global__ void k_out(const float* __restrict__ Wl, const float* __restrict__ bl,
                      float* __restrict__ out) {
    __shared__ float pooled[32];
    int g = blockIdx.x;
    if (threadIdx.x < 32) {
        float c = g_cnt[g];
        pooled[threadIdx.x] = g_pool[g * 32 + threadIdx.x] / fmaxf(c, 1.f);
    }
    __syncthreads();
    int o = threadIdx.x;  // 768 threads
    float acc = bl[o];
#pragma unroll
    for (int c = 0; c < 32; c++) acc = fmaf(pooled[c], Wl[c * 768 + o], acc);
    out[(size_t)g * 768 + o] = acc;
}

// ---------------- launch (fork/join: CSR build || layer-1 GEMM) ----------------
extern "C" void kernel_launch(void* const* d_in, const int* in_sizes, int n_in,
                              void* d_out, int out_size) {
    const float* x = (const float*)d_in[0];
    const void* ei = d_in[1];
    const float* ea = (const float*)d_in[2];
    const void* batch = d_in[3];
    const float* W1 = (const float*)d_in[4];
    const float* b1 = (const float*)d_in[5];
    const float* W2 = (const float*)d_in[6];
    const float* b2 = (const float*)d_in[7];
    const float* W3 = (const float*)d_in[8];
    const float* b3 = (const float*)d_in[9];
    const float* Wl = (const float*)d_in[10];
    const float* bl = (const float*)d_in[11];
    float* out = (float*)d_out;

    // Host-side objects, created once (no device memory involved).
    static cudaStream_t s2 = nullptr;
    static cudaEvent_t evFork = nullptr, evJoin = nullptr;
    if (!s2) {
        cudaStreamCreateWithFlags(&s2, cudaStreamNonBlocking);
        cudaEventCreateWithFlags(&evFork, cudaEventDisableTiming);
        cudaEventCreateWithFlags(&evJoin, cudaEventDisableTiming);
    }
    cudaStream_t s0 = cudaStreamPerThread;

    // Fork: side stream runs layer-1 GEMM (depends only on x, W1).
    cudaEventRecord(evFork, s0);
    cudaStreamWaitEvent(s2, evFork, 0);
    {
        dim3 grid(2, (NN + 63) / 64);
        k_gemm<<<grid, 256, 0, s2>>>(x, 0, W1, NN, 128, 128, /*relu=*/0);
        cudaEventRecord(evJoin, s2);
    }

    // Main stream: CSR build chain.
    k_init<<<(NN + 255) / 256, 256, 0, s0>>>((const unsigned int*)ei);
    k_prep<<<512, 256, 0, s0>>>(ei, ea);
    k_scan1<<<NBLK, SCAN_BLK, 0, s0>>>();
    k_scan2<<<1, SCAN_BLK, 0, s0>>>();
    k_scan3<<<NBLK, SCAN_BLK, 0, s0>>>();
    k_fill<<<(NE + 255) / 256, 0ull ? 0 : 256, 0, s0>>>(ea);

    // Join: gather-1 needs both H (s2) and CSR (s0).
    cudaStreamWaitEvent(s0, evJoin, 0);
    k_gather<32, 5><<<(NN * 32 + 255) / 256, 256, 0, s0>>>(b1);

    // Layer 2: relu(bufA) @ W2 -> H; gather -> bufA
    {
        dim3 grid(1, (NN + 63) / 64);
        k_gemm<<<grid, 256, 0, s0>>>(nullptr, 1, W2, NN, 128, 64, /*relu=*/1);
        k_gather<16, 4><<<(NN * 16 + 255) / 256, 256, 0, s0>>>(b2);
    }
    // Layer 3: relu(bufA) @ W3 -> H; gather fused with pool
    {
        dim3 grid(1, (NN + 63) / 64);
        k_gemm<<<grid, 256, 0, s0>>>(nullptr, 1, W3, NN, 64, 32, /*relu=*/1);
        k_gather_pool<<<(NN * 8 + 255) / 256, 256, 0, s0>>>(b3, batch);
    }
    k_out<<<NG, 768, 0, s0>>>(Wl, bl, out);
}

// round 8
// speedup vs baseline: 2.5900x; 1.1728x over previous
#include <cuda_runtime.h>
#include <cstdint>

#define NN 50000
#define NE 800000
#define NG 64
#define MAXF 128
#define SCAN_BLK 256
#define NBLK ((NN + SCAN_BLK - 1) / SCAN_BLK)   // 196

typedef unsigned long long ull;

// ---------------- scratch (device globals; no runtime allocation) ----------------
__device__ __align__(16) float g_bufA[NN * MAXF];
__device__ __align__(16) float g_h[NN * MAXF];
__device__ int   g_src[NE];
__device__ int   g_dst[NE];
__device__ int   g_csrc[NE];     // CSR-permuted src
__device__ float g_cnorm[NE];    // CSR-permuted norm
__device__ int   g_count[NN];    // in-degree
__device__ int   g_rowptr[NN + 1];
__device__ int   g_fill[NN];
__device__ int   g_blocksum[NBLK + 1];
__device__ float g_deg[NN];      // raw sum of ea per dst (scaled later)
__device__ float g_dinv[NN];
__device__ float g_invdeg[NN];
__device__ __align__(16) float g_pool[NG * 32];
__device__ float g_cnt[NG];
__device__ unsigned int g_maxbits;
__device__ unsigned int g_oddOr;   // 0 -> edge_index/batch are int64, else int32

// ---------------- packed f32x2 helpers ----------------
__device__ __forceinline__ ull pack2(float x, float y) {
    ull r; asm("mov.b64 %0, {%1,%2};" : "=l"(r) : "f"(x), "f"(y)); return r;
}
__device__ __forceinline__ void unpack2(ull v, float& x, float& y) {
    asm("mov.b64 {%0,%1}, %2;" : "=f"(x), "=f"(y) : "l"(v));
}
__device__ __forceinline__ void ffma2(ull& c, ull a, ull b) {
    asm("fma.rn.f32x2 %0, %1, %2, %0;" : "+l"(c) : "l"(a), "l"(b));
}

// ---------------- init + fast dtype detection ----------------
__global__ void k_init(const unsigned int* __restrict__ ei32) {
    int i = blockIdx.x * blockDim.x + threadIdx.x;
    if (i < NN) { g_deg[i] = 0.f; g_count[i] = 0; g_fill[i] = 0; }
    if (i < NG * 32) g_pool[i] = 0.f;
    if (i < NG) g_cnt[i] = 0.f;
    if (i == 0) { g_maxbits = 0u; g_oddOr = 0u; }
    if (blockIdx.x == 0) {
        __syncthreads();
        unsigned int v = 0;
        for (int t = threadIdx.x; t < 8192; t += blockDim.x)
            v |= ei32[2 * t + 1];
#pragma unroll
        for (int o = 16; o; o >>= 1) v |= __shfl_xor_sync(0xffffffffu, v, o);
        if ((threadIdx.x & 31) == 0 && v) atomicOr(&g_oddOr, v);
    }
}

// ---------------- fused per-edge pass: decode, max(ea), raw deg, count ----------------
__global__ void k_prep(const void* __restrict__ ei, const float* __restrict__ ea) {
    bool is64 = (g_oddOr == 0u);
    const long long* p64 = (const long long*)ei;
    const int* p32 = (const int*)ei;
    float m = 0.f;
    for (int e = blockIdx.x * blockDim.x + threadIdx.x; e < NE;
         e += gridDim.x * blockDim.x) {
        int s, d;
        if (is64) { s = (int)p64[e]; d = (int)p64[NE + e]; }
        else      { s = p32[e];      d = p32[NE + e]; }
        g_src[e] = s;
        g_dst[e] = d;
        float a = ea[e];
        m = fmaxf(m, a);
        atomicAdd(&g_deg[d], a);
        atomicAdd(&g_count[d], 1);
    }
#pragma unroll
    for (int o = 16; o; o >>= 1) m = fmaxf(m, __shfl_xor_sync(0xffffffffu, m, o));
    if ((threadIdx.x & 31) == 0) atomicMax(&g_maxbits, __float_as_uint(m));
}

// ---------------- scan phase 1 ----------------
__global__ void k_scan1() {
    __shared__ int wsum[SCAN_BLK / 32];
    int i = blockIdx.x * SCAN_BLK + threadIdx.x;
    int c = (i < NN) ? g_count[i] : 0;
    int lane = threadIdx.x & 31, wid = threadIdx.x >> 5;
    int v = c;
#pragma unroll
    for (int o = 1; o < 32; o <<= 1) {
        int u = __shfl_up_sync(0xffffffffu, v, o);
        if (lane >= o) v += u;
    }
    if (lane == 31) wsum[wid] = v;
    __syncthreads();
    if (wid == 0) {
        int w = (lane < SCAN_BLK / 32) ? wsum[lane] : 0;
#pragma unroll
        for (int o = 1; o < SCAN_BLK / 32; o <<= 1) {
            int u = __shfl_up_sync(0xffffffffu, w, o);
            if (lane >= o) w += u;
        }
        if (lane < SCAN_BLK / 32) wsum[lane] = w;
    }
    __syncthreads();
    int excl = v - c + (wid > 0 ? wsum[wid - 1] : 0);
    if (i < NN) g_rowptr[i] = excl;
    if (threadIdx.x == SCAN_BLK - 1) g_blocksum[blockIdx.x] = excl + c;
}

// ---------------- scan phase 2 ----------------
__global__ void k_scan2() {
    __shared__ int wsum[SCAN_BLK / 32];
    int i = threadIdx.x;
    int c = (i < NBLK) ? g_blocksum[i] : 0;
    int lane = i & 31, wid = i >> 5;
    int v = c;
#pragma unroll
    for (int o = 1; o < 32; o <<= 1) {
        int u = __shfl_up_sync(0xffffffffu, v, o);
        if (lane >= o) v += u;
    }
    if (lane == 31) wsum[wid] = v;
    __syncthreads();
    if (wid == 0) {
        int w = (lane < SCAN_BLK / 32) ? wsum[lane] : 0;
#pragma unroll
        for (int o = 1; o < SCAN_BLK / 32; o <<= 1) {
            int u = __shfl_up_sync(0xffffffffu, w, o);
            if (lane >= o) w += u;
        }
        if (lane < SCAN_BLK / 32) wsum[lane] = w;
    }
    __syncthreads();
    int excl = v - c + (wid > 0 ? wsum[wid - 1] : 0);
    if (i < NBLK) g_blocksum[i] = excl;
    if (i == 0) g_rowptr[NN] = NE;
}

// ---------------- scan phase 3: block offsets + node factors ----------------
__global__ void k_scan3() {
    int i = blockIdx.x * SCAN_BLK + threadIdx.x;
    if (i >= NN) return;
    g_rowptr[i] += g_blocksum[blockIdx.x];
    float invmax = 1.f / __uint_as_float(g_maxbits);
    float d = fmaf(g_deg[i], invmax, 1.f);
    g_dinv[i] = rsqrtf(d);
    g_invdeg[i] = 1.f / d;
}

// ---------------- fill CSR ----------------
__global__ void k_fill(const float* __restrict__ ea) {
    int e = blockIdx.x * blockDim.x + threadIdx.x;
    if (e >= NE) return;
    int s = g_src[e], d = g_dst[e];
    float invmax = 1.f / __uint_as_float(g_maxbits);
    float norm = g_dinv[s] * (ea[e] * invmax) * g_dinv[d];
    int pos = g_rowptr[d] + atomicAdd(&g_fill[d], 1);
    g_csrc[pos] = s;
    g_cnorm[pos] = norm;
}

// ---------------- 128xN-tiled fp32 GEMM, 8xTN register tiles, f32x2 FMA ----------------
// H = act(A) @ W.  BM=128, BK=16, 256 threads, thread tile 8 x TN (TN = BN/16).
template <int BN, int TN>
__global__ void k_gemm(const float* __restrict__ Aext, int useBufA,
                       const float* __restrict__ W, int M, int K, int reluIn) {
    __shared__ float As[16][132];        // [k][m] transposed; 132*4=528B row (16B-mult)
    __shared__ float Bs[16][BN + 4];     // [k][n]; (BN+4)*4 is 16B-mult for BN in {32,64,128}
    const float* A = useBufA ? g_bufA : Aext;
    float* H = g_h;

    int tid = threadIdx.x;
    int tr = tid >> 4;        // 0..15 -> rows tr*8..tr*8+7
    int tc = tid & 15;        // 0..15 -> cols tc*TN..
    int rowBase = blockIdx.y * 128;

    ull acc2[8][TN / 2];
#pragma unroll
    for (int i = 0; i < 8; i++)
#pragma unroll
        for (int j = 0; j < TN / 2; j++) acc2[i][j] = 0ull;

    for (int kt = 0; kt < K; kt += 16) {
        // load A tile 128x16 -> As transposed ([k][m])
#pragma unroll
        for (int idx = tid; idx < 512; idx += 256) {
            int r = idx >> 2;            // 0..127
            int c4 = (idx & 3) * 4;      // 0,4,8,12
            int ar = rowBase + r;
            float4 v = make_float4(0.f, 0.f, 0.f, 0.f);
            if (ar < M) v = *(const float4*)(A + (size_t)ar * K + kt + c4);
            if (reluIn) {
                v.x = fmaxf(v.x, 0.f); v.y = fmaxf(v.y, 0.f);
                v.z = fmaxf(v.z, 0.f); v.w = fmaxf(v.w, 0.f);
            }
            As[c4 + 0][r] = v.x; As[c4 + 1][r] = v.y;
            As[c4 + 2][r] = v.z; As[c4 + 3][r] = v.w;
        }
        // load B tile 16xBN ([k][n]); W is K x BN (N == BN, grid.x == 1)
        constexpr int F4R = BN / 4;
#pragma unroll
        for (int idx = tid; idx < 16 * F4R; idx += 256) {
            int r = idx / F4R;
            int c = (idx % F4R) * 4;
            float4 v = *(const float4*)(W + (size_t)(kt + r) * BN + c);
            *(float4*)&Bs[r][c] = v;
        }
        __syncthreads();

#pragma unroll
        for (int kk = 0; kk < 16; kk++) {
            float a[8];
            *(float4*)&a[0] = *(const float4*)&As[kk][tr * 8];
            *(float4*)&a[4] = *(const float4*)&As[kk][tr * 8 + 4];
            ull bp[TN / 2];
#pragma unroll
            for (int j = 0; j < TN / 2; j++)
                bp[j] = *(const ull*)&Bs[kk][tc * TN + 2 * j];
#pragma unroll
            for (int i = 0; i < 8; i++) {
                ull aa = pack2(a[i], a[i]);
#pragma unroll
                for (int j = 0; j < TN / 2; j++) ffma2(acc2[i][j], aa, bp[j]);
            }
        }
        __syncthreads();
    }

#pragma unroll
    for (int i = 0; i < 8; i++) {
        int r = rowBase + tr * 8 + i;
        if (r >= M) continue;
        float o[TN];
#pragma unroll
        for (int j = 0; j < TN / 2; j++) unpack2(acc2[i][j], o[2 * j], o[2 * j + 1]);
        float* dst = H + (size_t)r * BN + tc * TN;
        if (TN == 8) {
            *(float4*)dst = *(float4*)&o[0];
            *(float4*)(dst + 4) = *(float4*)&o[4];
        } else if (TN == 4) {
            *(float4*)dst = *(float4*)&o[0];
        } else {
            *(float2*)dst = *(float2*)&o[0];
        }
    }
}

// ---------------- gather (unrolled x4): AGG[n] = H[n]*invdeg + bias + sum norm*H[src] ----------------
template <int VEC, int SHIFT>
__global__ void k_gather(const float* __restrict__ bias) {
    int t = blockIdx.x * blockDim.x + threadIdx.x;
    if (t >= NN * VEC) return;
    int n = t >> SHIFT;
    int j = t & (VEC - 1);
    int beg = g_rowptr[n];
    int end = g_rowptr[n + 1];
    const float4* __restrict__ H4 = (const float4*)g_h;
    const int* __restrict__ csrc = g_csrc;
    const float* __restrict__ cnorm = g_cnorm;
    float4* AGG4 = (float4*)g_bufA;

    float id = g_invdeg[n];
    float4 b = *(const float4*)(bias + j * 4);
    float4 hv = H4[(size_t)n * VEC + j];
    float4 acc;
    acc.x = fmaf(hv.x, id, b.x);
    acc.y = fmaf(hv.y, id, b.y);
    acc.z = fmaf(hv.z, id, b.z);
    acc.w = fmaf(hv.w, id, b.w);

    int k = beg;
    for (; k + 4 <= end; k += 4) {
        int s0 = csrc[k], s1 = csrc[k + 1], s2 = csrc[k + 2], s3 = csrc[k + 3];
        float n0 = cnorm[k], n1 = cnorm[k + 1], n2 = cnorm[k + 2], n3 = cnorm[k + 3];
        float4 v0 = H4[(size_t)s0 * VEC + j];
        float4 v1 = H4[(size_t)s1 * VEC + j];
        float4 v2 = H4[(size_t)s2 * VEC + j];
        float4 v3 = H4[(size_t)s3 * VEC + j];
        acc.x = fmaf(n0, v0.x, acc.x); acc.y = fmaf(n0, v0.y, acc.y);
        acc.z = fmaf(n0, v0.z, acc.z); acc.w = fmaf(n0, v0.w, acc.w);
        acc.x = fmaf(n1, v1.x, acc.x); acc.y = fmaf(n1, v1.y, acc.y);
        acc.z = fmaf(n1, v1.z, acc.z); acc.w = fmaf(n1, v1.w, acc.w);
        acc.x = fmaf(n2, v2.x, acc.x); acc.y = fmaf(n2, v2.y, acc.y);
        acc.z = fmaf(n2, v2.z, acc.z); acc.w = fmaf(n2, v2.w, acc.w);
        acc.x = fmaf(n3, v3.x, acc.x); acc.y = fmaf(n3, v3.y, acc.y);
        acc.z = fmaf(n3, v3.z, acc.z); acc.w = fmaf(n3, v3.w, acc.w);
    }
    for (; k < end; k++) {
        int s = csrc[k];
        float nm = cnorm[k];
        float4 v = H4[(size_t)s * VEC + j];
        acc.x = fmaf(nm, v.x, acc.x);
        acc.y = fmaf(nm, v.y, acc.y);
        acc.z = fmaf(nm, v.z, acc.z);
        acc.w = fmaf(nm, v.w, acc.w);
    }
    AGG4[(size_t)n * VEC + j] = acc;
}

// ---------------- layer-3 gather fused with relu + mean-pool accumulation ----------------
__global__ void k_gather_pool(const float* __restrict__ bias,
                              const void* __restrict__ batch) {
    int t = blockIdx.x * blockDim.x + threadIdx.x;
    if (t >= NN * 8) return;
    int n = t >> 3;
    int j = t & 7;
    int beg = g_rowptr[n];
    int end = g_rowptr[n + 1];
    const float4* __restrict__ H4 = (const float4*)g_h;
    const int* __restrict__ csrc = g_csrc;
    const float* __restrict__ cnorm = g_cnorm;

    float id = g_invdeg[n];
    float4 b = *(const float4*)(bias + j * 4);
    float4 hv = H4[(size_t)n * 8 + j];
    float4 acc;
    acc.x = fmaf(hv.x, id, b.x);
    acc.y = fmaf(hv.y, id, b.y);
    acc.z = fmaf(hv.z, id, b.z);
    acc.w = fmaf(hv.w, id, b.w);

    int k = beg;
    for (; k + 4 <= end; k += 4) {
        int s0 = csrc[k], s1 = csrc[k + 1], s2 = csrc[k + 2], s3 = csrc[k + 3];
        float n0 = cnorm[k], n1 = cnorm[k + 1], n2 = cnorm[k + 2], n3 = cnorm[k + 3];
        float4 v0 = H4[(size_t)s0 * 8 + j];
        float4 v1 = H4[(size_t)s1 * 8 + j];
        float4 v2 = H4[(size_t)s2 * 8 + j];
        float4 v3 = H4[(size_t)s3 * 8 + j];
        acc.x = fmaf(n0, v0.x, acc.x); acc.y = fmaf(n0, v0.y, acc.y);
        acc.z = fmaf(n0, v0.z, acc.z); acc.w = fmaf(n0, v0.w, acc.w);
        acc.x = fmaf(n1, v1.x, acc.x); acc.y = fmaf(n1, v1.y, acc.y);
        acc.z = fmaf(n1, v1.z, acc.z); acc.w = fmaf(n1, v1.w, acc.w);
        acc.x = fmaf(n2, v2.x, acc.x); acc.y = fmaf(n2, v2.y, acc.y);
        acc.z = fmaf(n2, v2.z, acc.z); acc.w = fmaf(n2, v2.w, acc.w);
        acc.x = fmaf(n3, v3.x, acc.x); acc.y = fmaf(n3, v3.y, acc.y);
        acc.z = fmaf(n3, v3.z, acc.z); acc.w = fmaf(n3, v3.w, acc.w);
    }
    for (; k < end; k++) {
        int s = csrc[k];
        float nm = cnorm[k];
        float4 v = H4[(size_t)s * 8 + j];
        acc.x = fmaf(nm, v.x, acc.x);
        acc.y = fmaf(nm, v.y, acc.y);
        acc.z = fmaf(nm, v.z, acc.z);
        acc.w = fmaf(nm, v.w, acc.w);
    }

    int g;
    if (g_oddOr == 0u) g = (int)((const long long*)batch)[n];
    else               g = ((const int*)batch)[n];
    float* p = &g_pool[g * 32 + j * 4];
    atomicAdd(p + 0, fmaxf(acc.x, 0.f));
    atomicAdd(p + 1, fmaxf(acc.y, 0.f));
    atomicAdd(p + 2, fmaxf(acc.z, 0.f));
    atomicAdd(p + 3, fmaxf(acc.w, 0.f));
    if (j == 0) atomicAdd(&g_cnt[g], 1.f);
}

// ---------------- head ----------------
__global__ void k_out(const float* __restrict__ Wl, const float* __restrict__ bl,
                      float* __restrict__ out) {
    __shared__ float pooled[32];
    int g = blockIdx.x;
    if (threadIdx.x < 32) {
        float c = g_cnt[g];
        pooled[threadIdx.x] = g_pool[g * 32 + threadIdx.x] / fmaxf(c, 1.f);
    }
    __syncthreads();
    int o = threadIdx.x;  // 768 threads
    float acc = bl[o];
#pragma unroll
    for (int c = 0; c < 32; c++) acc = fmaf(pooled[c], Wl[c * 768 + o], acc);
    out[(size_t)g * 768 + o] = acc;
}

// ---------------- launch (fork/join: CSR build || layer-1 GEMM) ----------------
extern "C" void kernel_launch(void* const* d_in, const int* in_sizes, int n_in,
                              void* d_out, int out_size) {
    const float* x = (const float*)d_in[0];
    const void* ei = d_in[1];
    const float* ea = (const float*)d_in[2];
    const void* batch = d_in[3];
    const float* W1 = (const float*)d_in[4];
    const float* b1 = (const float*)d_in[5];
    const float* W2 = (const float*)d_in[6];
    const float* b2 = (const float*)d_in[7];
    const float* W3 = (const float*)d_in[8];
    const float* b3 = (const float*)d_in[9];
    const float* Wl = (const float*)d_in[10];
    const float* bl = (const float*)d_in[11];
    float* out = (float*)d_out;

    static cudaStream_t s2 = nullptr;
    static cudaEvent_t evFork = nullptr, evJoin = nullptr;
    if (!s2) {
        cudaStreamCreateWithFlags(&s2, cudaStreamNonBlocking);
        cudaEventCreateWithFlags(&evFork, cudaEventDisableTiming);
        cudaEventCreateWithFlags(&evJoin, cudaEventDisableTiming);
    }
    cudaStream_t s0 = cudaStreamPerThread;

    // Fork: side stream runs layer-1 GEMM (depends only on x, W1).
    cudaEventRecord(evFork, s0);
    cudaStreamWaitEvent(s2, evFork, 0);
    {
        dim3 grid(1, (NN + 127) / 128);
        k_gemm<128, 8><<<grid, 256, 0, s2>>>(x, 0, W1, NN, 128, /*relu=*/0);
        cudaEventRecord(evJoin, s2);
    }

    // Main stream: CSR build chain.
    k_init<<<(NN + 255) / 256, 256, 0, s0>>>((const unsigned int*)ei);
    k_prep<<<512, 256, 0, s0>>>(ei, ea);
    k_scan1<<<NBLK, SCAN_BLK, 0, s0>>>();
    k_scan2<<<1, SCAN_BLK, 0, s0>>>();
    k_scan3<<<NBLK, SCAN_BLK, 0, s0>>>();
    k_fill<<<(NE + 255) / 256, 256, 0, s0>>>(ea);

    // Join: gather-1 needs both H (s2) and CSR (s0).
    cudaStreamWaitEvent(s0, evJoin, 0);
    k_gather<32, 5><<<(NN * 32 + 255) / 256, 256, 0, s0>>>(b1);

    // Layer 2: relu(bufA) @ W2 -> H; gather -> bufA
    {
        dim3 grid(1, (NN + 127) / 128);
        k_gemm<64, 4><<<grid, 256, 0, s0>>>(nullptr, 1, W2, NN, 128, /*relu=*/1);
        k_gather<16, 4><<<(NN * 16 + 255) / 256, 256, 0, s0>>>(b2);
    }
    // Layer 3: relu(bufA) @ W3 -> H; gather fused with pool
    {
        dim3 grid(1, (NN + 127) / 128);
        k_gemm<32, 2><<<grid, 256, 0, s0>>>(nullptr, 1, W3, NN, 64, /*relu=*/1);
        k_gather_pool<<<(NN * 8 + 255) / 256, 256, 0, s0>>>(b3, batch);
    }
    k_out<<<NG, 768, 0, s0>>>(Wl, bl, out);
}

// round 9
// speedup vs baseline: 2.5903x; 1.0001x over previous
#include <cuda_runtime.h>
#include <cstdint>

#define NN 50000
#define NE 800000
#define NG 64
#define MAXF 128
#define SCAN_BLK 256
#define NBLK ((NN + SCAN_BLK - 1) / SCAN_BLK)   // 196

typedef unsigned long long ull;

// ---------------- scratch (device globals; no runtime allocation) ----------------
__device__ __align__(16) float g_bufA[NN * MAXF];
__device__ __align__(16) float g_h[NN * MAXF];
__device__ int   g_src[NE];
__device__ int   g_dst[NE];
__device__ ull   g_edge[NE];     // CSR-permuted (src | norm<<32)
__device__ int   g_count[NN];    // in-degree
__device__ int   g_rowptr[NN];   // bucket base (non-monotone across blocks; end = base+count)
__device__ int   g_fill[NN];
__device__ float g_deg[NN];      // raw sum of ea per dst (scaled later)
__device__ float g_dinv[NN];
__device__ float g_invdeg[NN];
__device__ __align__(16) float g_pool[NG * 32];
__device__ float g_cnt[NG];
__device__ unsigned int g_maxbits;
__device__ unsigned int g_oddOr;   // 0 -> edge_index/batch are int64, else int32
__device__ int g_total;            // atomic bucket-range allocator

// ---------------- packed f32x2 helpers ----------------
__device__ __forceinline__ ull pack2(float x, float y) {
    ull r; asm("mov.b64 %0, {%1,%2};" : "=l"(r) : "f"(x), "f"(y)); return r;
}
__device__ __forceinline__ void unpack2(ull v, float& x, float& y) {
    asm("mov.b64 {%0,%1}, %2;" : "=f"(x), "=f"(y) : "l"(v));
}
__device__ __forceinline__ void ffma2(ull& c, ull a, ull b) {
    asm("fma.rn.f32x2 %0, %1, %2, %0;" : "+l"(c) : "l"(a), "l"(b));
}

// ---------------- init + fast dtype detection ----------------
__global__ void k_init(const unsigned int* __restrict__ ei32) {
    int i = blockIdx.x * blockDim.x + threadIdx.x;
    if (i < NN) { g_deg[i] = 0.f; g_count[i] = 0; g_fill[i] = 0; }
    if (i < NG * 32) g_pool[i] = 0.f;
    if (i < NG) g_cnt[i] = 0.f;
    if (i == 0) { g_maxbits = 0u; g_oddOr = 0u; g_total = 0; }
    if (blockIdx.x == 0) {
        __syncthreads();
        unsigned int v = 0;
        for (int t = threadIdx.x; t < 8192; t += blockDim.x)
            v |= ei32[2 * t + 1];
#pragma unroll
        for (int o = 16; o; o >>= 1) v |= __shfl_xor_sync(0xffffffffu, v, o);
        if ((threadIdx.x & 31) == 0 && v) atomicOr(&g_oddOr, v);
    }
}

// ---------------- fused per-edge pass: decode, max(ea), raw deg, count ----------------
__global__ void k_prep(const void* __restrict__ ei, const float* __restrict__ ea) {
    bool is64 = (g_oddOr == 0u);
    const long long* p64 = (const long long*)ei;
    const int* p32 = (const int*)ei;
    float m = 0.f;
    for (int e = blockIdx.x * blockDim.x + threadIdx.x; e < NE;
         e += gridDim.x * blockDim.x) {
        int s, d;
        if (is64) { s = (int)p64[e]; d = (int)p64[NE + e]; }
        else      { s = p32[e];      d = p32[NE + e]; }
        g_src[e] = s;
        g_dst[e] = d;
        float a = ea[e];
        m = fmaxf(m, a);
        atomicAdd(&g_deg[d], a);
        atomicAdd(&g_count[d], 1);
    }
#pragma unroll
    for (int o = 16; o; o >>= 1) m = fmaxf(m, __shfl_xor_sync(0xffffffffu, m, o));
    if ((threadIdx.x & 31) == 0) atomicMax(&g_maxbits, __float_as_uint(m));
}

// ---------------- single-pass bucket allocation + node factors ----------------
// Each block: local exclusive scan of 256 counts, atomically grabs a global
// range for its total. rowptr[i] = blockBase + localExcl (non-monotone across
// blocks — fine, since gather uses end = rowptr[n] + count[n]).
__global__ void k_scanA() {
    __shared__ int wsum[SCAN_BLK / 32];
    __shared__ int sbase;
    int i = blockIdx.x * SCAN_BLK + threadIdx.x;
    int c = (i < NN) ? g_count[i] : 0;
    int lane = threadIdx.x & 31, wid = threadIdx.x >> 5;
    int v = c;
#pragma unroll
    for (int o = 1; o < 32; o <<= 1) {
        int u = __shfl_up_sync(0xffffffffu, v, o);
        if (lane >= o) v += u;
    }
    if (lane == 31) wsum[wid] = v;
    __syncthreads();
    if (wid == 0) {
        int w = (lane < SCAN_BLK / 32) ? wsum[lane] : 0;
#pragma unroll
        for (int o = 1; o < SCAN_BLK / 32; o <<= 1) {
            int u = __shfl_up_sync(0xffffffffu, w, o);
            if (lane >= o) w += u;
        }
        if (lane < SCAN_BLK / 32) wsum[lane] = w;
    }
    __syncthreads();
    if (threadIdx.x == 0) sbase = atomicAdd(&g_total, wsum[SCAN_BLK / 32 - 1]);
    __syncthreads();
    if (i < NN) {
        int excl = v - c + (wid > 0 ? wsum[wid - 1] : 0);
        g_rowptr[i] = sbase + excl;
        float invmax = 1.f / __uint_as_float(g_maxbits);
        float d = fmaf(g_deg[i], invmax, 1.f);
        g_dinv[i] = rsqrtf(d);
        g_invdeg[i] = 1.f / d;
    }
}

// ---------------- fill CSR: one packed 8B store per edge ----------------
__global__ void k_fill(const float* __restrict__ ea) {
    int e = blockIdx.x * blockDim.x + threadIdx.x;
    if (e >= NE) return;
    int s = g_src[e], d = g_dst[e];
    float invmax = 1.f / __uint_as_float(g_maxbits);
    float norm = g_dinv[s] * (ea[e] * invmax) * g_dinv[d];
    int pos = g_rowptr[d] + atomicAdd(&g_fill[d], 1);
    g_edge[pos] = (ull)(unsigned int)s | ((ull)__float_as_uint(norm) << 32);
}

// ---------------- 128xN-tiled fp32 GEMM, 8xTN register tiles, f32x2 FMA ----------------
template <int BN, int TN>
__global__ void k_gemm(const float* __restrict__ Aext, int useBufA,
                       const float* __restrict__ W, int M, int K, int reluIn) {
    __shared__ float As[16][132];
    __shared__ float Bs[16][BN + 4];
    const float* A = useBufA ? g_bufA : Aext;
    float* H = g_h;

    int tid = threadIdx.x;
    int tr = tid >> 4;
    int tc = tid & 15;
    int rowBase = blockIdx.y * 128;

    ull acc2[8][TN / 2];
#pragma unroll
    for (int i = 0; i < 8; i++)
#pragma unroll
        for (int j = 0; j < TN / 2; j++) acc2[i][j] = 0ull;

    for (int kt = 0; kt < K; kt += 16) {
#pragma unroll
        for (int idx = tid; idx < 512; idx += 256) {
            int r = idx >> 2;
            int c4 = (idx & 3) * 4;
            int ar = rowBase + r;
            float4 v = make_float4(0.f, 0.f, 0.f, 0.f);
            if (ar < M) v = *(const float4*)(A + (size_t)ar * K + kt + c4);
            if (reluIn) {
                v.x = fmaxf(v.x, 0.f); v.y = fmaxf(v.y, 0.f);
                v.z = fmaxf(v.z, 0.f); v.w = fmaxf(v.w, 0.f);
            }
            As[c4 + 0][r] = v.x; As[c4 + 1][r] = v.y;
            As[c4 + 2][r] = v.z; As[c4 + 3][r] = v.w;
        }
        constexpr int F4R = BN / 4;
#pragma unroll
        for (int idx = tid; idx < 16 * F4R; idx += 256) {
            int r = idx / F4R;
            int c = (idx % F4R) * 4;
            float4 v = *(const float4*)(W + (size_t)(kt + r) * BN + c);
            *(float4*)&Bs[r][c] = v;
        }
        __syncthreads();

#pragma unroll
        for (int kk = 0; kk < 16; kk++) {
            float a[8];
            *(float4*)&a[0] = *(const float4*)&As[kk][tr * 8];
            *(float4*)&a[4] = *(const float4*)&As[kk][tr * 8 + 4];
            ull bp[TN / 2];
#pragma unroll
            for (int j = 0; j < TN / 2; j++)
                bp[j] = *(const ull*)&Bs[kk][tc * TN + 2 * j];
#pragma unroll
            for (int i = 0; i < 8; i++) {
                ull aa = pack2(a[i], a[i]);
#pragma unroll
                for (int j = 0; j < TN / 2; j++) ffma2(acc2[i][j], aa, bp[j]);
            }
        }
        __syncthreads();
    }

#pragma unroll
    for (int i = 0; i < 8; i++) {
        int r = rowBase + tr * 8 + i;
        if (r >= M) continue;
        float o[TN];
#pragma unroll
        for (int j = 0; j < TN / 2; j++) unpack2(acc2[i][j], o[2 * j], o[2 * j + 1]);
        float* dst = H + (size_t)r * BN + tc * TN;
        if (TN == 8) {
            *(float4*)dst = *(float4*)&o[0];
            *(float4*)(dst + 4) = *(float4*)&o[4];
        } else if (TN == 4) {
            *(float4*)dst = *(float4*)&o[0];
        } else {
            *(float2*)dst = *(float2*)&o[0];
        }
    }
}

// ---------------- gather (unrolled x4, packed edges) ----------------
template <int VEC, int SHIFT>
__global__ void k_gather(const float* __restrict__ bias) {
    int t = blockIdx.x * blockDim.x + threadIdx.x;
    if (t >= NN * VEC) return;
    int n = t >> SHIFT;
    int j = t & (VEC - 1);
    int beg = g_rowptr[n];
    int end = beg + g_count[n];
    const float4* __restrict__ H4 = (const float4*)g_h;
    const ull* __restrict__ edge = g_edge;
    float4* AGG4 = (float4*)g_bufA;

    float id = g_invdeg[n];
    float4 b = *(const float4*)(bias + j * 4);
    float4 hv = H4[(size_t)n * VEC + j];
    float4 acc;
    acc.x = fmaf(hv.x, id, b.x);
    acc.y = fmaf(hv.y, id, b.y);
    acc.z = fmaf(hv.z, id, b.z);
    acc.w = fmaf(hv.w, id, b.w);

    int k = beg;
    for (; k + 4 <= end; k += 4) {
        ull e0 = edge[k], e1 = edge[k + 1], e2 = edge[k + 2], e3 = edge[k + 3];
        float n0 = __uint_as_float((unsigned int)(e0 >> 32));
        float n1 = __uint_as_float((unsigned int)(e1 >> 32));
        float n2 = __uint_as_float((unsigned int)(e2 >> 32));
        float n3 = __uint_as_float((unsigned int)(e3 >> 32));
        float4 v0 = H4[(size_t)(unsigned int)e0 * VEC + j];
        float4 v1 = H4[(size_t)(unsigned int)e1 * VEC + j];
        float4 v2 = H4[(size_t)(unsigned int)e2 * VEC + j];
        float4 v3 = H4[(size_t)(unsigned int)e3 * VEC + j];
        acc.x = fmaf(n0, v0.x, acc.x); acc.y = fmaf(n0, v0.y, acc.y);
        acc.z = fmaf(n0, v0.z, acc.z); acc.w = fmaf(n0, v0.w, acc.w);
        acc.x = fmaf(n1, v1.x, acc.x); acc.y = fmaf(n1, v1.y, acc.y);
        acc.z = fmaf(n1, v1.z, acc.z); acc.w = fmaf(n1, v1.w, acc.w);
        acc.x = fmaf(n2, v2.x, acc.x); acc.y = fmaf(n2, v2.y, acc.y);
        acc.z = fmaf(n2, v2.z, acc.z); acc.w = fmaf(n2, v2.w, acc.w);
        acc.x = fmaf(n3, v3.x, acc.x); acc.y = fmaf(n3, v3.y, acc.y);
        acc.z = fmaf(n3, v3.z, acc.z); acc.w = fmaf(n3, v3.w, acc.w);
    }
    for (; k < end; k++) {
        ull e0 = edge[k];
        float nm = __uint_as_float((unsigned int)(e0 >> 32));
        float4 v = H4[(size_t)(unsigned int)e0 * VEC + j];
        acc.x = fmaf(nm, v.x, acc.x);
        acc.y = fmaf(nm, v.y, acc.y);
        acc.z = fmaf(nm, v.z, acc.z);
        acc.w = fmaf(nm, v.w, acc.w);
    }
    AGG4[(size_t)n * VEC + j] = acc;
}

// ---------------- layer-3 gather fused with relu + mean-pool accumulation ----------------
__global__ void k_gather_pool(const float* __restrict__ bias,
                              const void* __restrict__ batch) {
    int t = blockIdx.x * blockDim.x + threadIdx.x;
    if (t >= NN * 8) return;
    int n = t >> 3;
    int j = t & 7;
    int beg = g_rowptr[n];
    int end = beg + g_count[n];
    const float4* __restrict__ H4 = (const float4*)g_h;
    const ull* __restrict__ edge = g_edge;

    float id = g_invdeg[n];
    float4 b = *(const float4*)(bias + j * 4);
    float4 hv = H4[(size_t)n * 8 + j];
    float4 acc;
    acc.x = fmaf(hv.x, id, b.x);
    acc.y = fmaf(hv.y, id, b.y);
    acc.z = fmaf(hv.z, id, b.z);
    acc.w = fmaf(hv.w, id, b.w);

    int k = beg;
    for (; k + 4 <= end; k += 4) {
        ull e0 = edge[k], e1 = edge[k + 1], e2 = edge[k + 2], e3 = edge[k + 3];
        float n0 = __uint_as_float((unsigned int)(e0 >> 32));
        float n1 = __uint_as_float((unsigned int)(e1 >> 32));
        float n2 = __uint_as_float((unsigned int)(e2 >> 32));
        float n3 = __uint_as_float((unsigned int)(e3 >> 32));
        float4 v0 = H4[(size_t)(unsigned int)e0 * 8 + j];
        float4 v1 = H4[(size_t)(unsigned int)e1 * 8 + j];
        float4 v2 = H4[(size_t)(unsigned int)e2 * 8 + j];
        float4 v3 = H4[(size_t)(unsigned int)e3 * 8 + j];
        acc.x = fmaf(n0, v0.x, acc.x); acc.y = fmaf(n0, v0.y, acc.y);
        acc.z = fmaf(n0, v0.z, acc.z); acc.w = fmaf(n0, v0.w, acc.w);
        acc.x = fmaf(n1, v1.x, acc.x); acc.y = fmaf(n1, v1.y, acc.y);
        acc.z = fmaf(n1, v1.z, acc.z); acc.w = fmaf(n1, v1.w, acc.w);
        acc.x = fmaf(n2, v2.x, acc.x); acc.y = fmaf(n2, v2.y, acc.y);
        acc.z = fmaf(n2, v2.z, acc.z); acc.w = fmaf(n2, v2.w, acc.w);
        acc.x = fmaf(n3, v3.x, acc.x); acc.y = fmaf(n3, v3.y, acc.y);
        acc.z = fmaf(n3, v3.z, acc.z); acc.w = fmaf(n3, v3.w, acc.w);
    }
    for (; k < end; k++) {
        ull e0 = edge[k];
        float nm = __uint_as_float((unsigned int)(e0 >> 32));
        float4 v = H4[(size_t)(unsigned int)e0 * 8 + j];
        acc.x = fmaf(nm, v.x, acc.x);
        acc.y = fmaf(nm, v.y, acc.y);
        acc.z = fmaf(nm, v.z, acc.z);
        acc.w = fmaf(nm, v.w, acc.w);
    }

    int g;
    if (g_oddOr == 0u) g = (int)((const long long*)batch)[n];
    else               g = ((const int*)batch)[n];
    float* p = &g_pool[g * 32 + j * 4];
    atomicAdd(p + 0, fmaxf(acc.x, 0.f));
    atomicAdd(p + 1, fmaxf(acc.y, 0.f));
    atomicAdd(p + 2, fmaxf(acc.z, 0.f));
    atomicAdd(p + 3, fmaxf(acc.w, 0.f));
    if (j == 0) atomicAdd(&g_cnt[g], 1.f);
}

// ---------------- head ----------------
__global__ void k_out(const float* __restrict__ Wl, const float* __restrict__ bl,
                      float* __restrict__ out) {
    __shared__ float pooled[32];
    int g = blockIdx.x;
    if (threadIdx.x < 32) {
        float c = g_cnt[g];
        pooled[threadIdx.x] = g_pool[g * 32 + threadIdx.x] / fmaxf(c, 1.f);
    }
    __syncthreads();
    int o = threadIdx.x;  // 768 threads
    float acc = bl[o];
#pragma unroll
    for (int c = 0; c < 32; c++) acc = fmaf(pooled[c], Wl[c * 768 + o], acc);
    out[(size_t)g * 768 + o] = acc;
}

// ---------------- launch (fork/join: CSR build || layer-1 GEMM) ----------------
extern "C" void kernel_launch(void* const* d_in, const int* in_sizes, int n_in,
                              void* d_out, int out_size) {
    const float* x = (const float*)d_in[0];
    const void* ei = d_in[1];
    const float* ea = (const float*)d_in[2];
    const void* batch = d_in[3];
    const float* W1 = (const float*)d_in[4];
    const float* b1 = (const float*)d_in[5];
    const float* W2 = (const float*)d_in[6];
    const float* b2 = (const float*)d_in[7];
    const float* W3 = (const float*)d_in[8];
    const float* b3 = (const float*)d_in[9];
    const float* Wl = (const float*)d_in[10];
    const float* bl = (const float*)d_in[11];
    float* out = (float*)d_out;

    static cudaStream_t s2 = nullptr;
    static cudaEvent_t evFork = nullptr, evJoin = nullptr;
    if (!s2) {
        cudaStreamCreateWithFlags(&s2, cudaStreamNonBlocking);
        cudaEventCreateWithFlags(&evFork, cudaEventDisableTiming);
        cudaEventCreateWithFlags(&evJoin, cudaEventDisableTiming);
    }
    cudaStream_t s0 = cudaStreamPerThread;

    // Fork: side stream runs layer-1 GEMM (depends only on x, W1).
    cudaEventRecord(evFork, s0);
    cudaStreamWaitEvent(s2, evFork, 0);
    {
        dim3 grid(1, (NN + 127) / 128);
        k_gemm<128, 8><<<grid, 256, 0, s2>>>(x, 0, W1, NN, 128, /*relu=*/0);
        cudaEventRecord(evJoin, s2);
    }

    // Main stream: CSR build chain.
    k_init<<<(NN + 255) / 256, 256, 0, s0>>>((const unsigned int*)ei);
    k_prep<<<512, 256, 0, s0>>>(ei, ea);
    k_scanA<<<NBLK, SCAN_BLK, 0, s0>>>();
    k_fill<<<(NE + 255) / 256, 256, 0, s0>>>(ea);

    // Join: gather-1 needs both H (s2) and CSR (s0).
    cudaStreamWaitEvent(s0, evJoin, 0);
    k_gather<32, 5><<<(NN * 32 + 255) / 256, 256, 0, s0>>>(b1);

    // Layer 2: relu(bufA) @ W2 -> H; gather -> bufA
    {
        dim3 grid(1, (NN + 127) / 128);
        k_gemm<64, 4><<<grid, 256, 0, s0>>>(nullptr, 1, W2, NN, 128, /*relu=*/1);
        k_gather<16, 4><<<(NN * 16 + 255) / 256, 256, 0, s0>>>(b2);
    }
    // Layer 3: relu(bufA) @ W3 -> H; gather fused with pool
    {
        dim3 grid(1, (NN + 127) / 128);
        k_gemm<32, 2><<<grid, 256, 0, s0>>>(nullptr, 1, W3, NN, 64, /*relu=*/1);
        k_gather_pool<<<(NN * 8 + 255) / 256, 256, 0, s0>>>(b3, batch);
    }
    k_out<<<NG, 768, 0, s0>>>(Wl, bl, out);
}

// round 10
// speedup vs baseline: 2.7474x; 1.0606x over previous
#include <cuda_runtime.h>
#include <cuda_fp16.h>
#include <cstdint>

#define NN 50000
#define NE 800000
#define NG 64
#define MAXF 128
#define SCAN_BLK 256
#define NBLK ((NN + SCAN_BLK - 1) / SCAN_BLK)   // 196

typedef unsigned long long ull;

// ---------------- scratch (device globals; no runtime allocation) ----------------
__device__ __align__(16) float g_bufA[NN * MAXF];
__device__ __align__(16) float g_h[NN * MAXF];        // fp32 H (layer 3)
__device__ __align__(16) __half g_h16[NN * MAXF];     // fp16 H (layers 1,2)
__device__ int   g_src[NE];
__device__ int   g_dst[NE];
__device__ ull   g_edge[NE];     // CSR-permuted (src | norm<<32)
__device__ int   g_count[NN];
__device__ int   g_rowptr[NN];   // bucket base (end = base + count)
__device__ int   g_fill[NN];
__device__ float g_deg[NN];
__device__ float g_dinv[NN];
__device__ float g_invdeg[NN];
__device__ __align__(16) float g_pool[NG * 32];
__device__ float g_cnt[NG];
__device__ unsigned int g_maxbits;
__device__ unsigned int g_oddOr;
__device__ int g_total;

// ---------------- packed f32x2 helpers ----------------
__device__ __forceinline__ ull pack2(float x, float y) {
    ull r; asm("mov.b64 %0, {%1,%2};" : "=l"(r) : "f"(x), "f"(y)); return r;
}
__device__ __forceinline__ void unpack2(ull v, float& x, float& y) {
    asm("mov.b64 {%0,%1}, %2;" : "=f"(x), "=f"(y) : "l"(v));
}
__device__ __forceinline__ void ffma2(ull& c, ull a, ull b) {
    asm("fma.rn.f32x2 %0, %1, %2, %0;" : "+l"(c) : "l"(a), "l"(b));
}

// ---------------- init + fast dtype detection ----------------
__global__ void k_init(const unsigned int* __restrict__ ei32) {
    int i = blockIdx.x * blockDim.x + threadIdx.x;
    if (i < NN) { g_deg[i] = 0.f; g_count[i] = 0; g_fill[i] = 0; }
    if (i < NG * 32) g_pool[i] = 0.f;
    if (i < NG) g_cnt[i] = 0.f;
    if (i == 0) { g_maxbits = 0u; g_oddOr = 0u; g_total = 0; }
    if (blockIdx.x == 0) {
        __syncthreads();
        unsigned int v = 0;
        for (int t = threadIdx.x; t < 8192; t += blockDim.x)
            v |= ei32[2 * t + 1];
#pragma unroll
        for (int o = 16; o; o >>= 1) v |= __shfl_xor_sync(0xffffffffu, v, o);
        if ((threadIdx.x & 31) == 0 && v) atomicOr(&g_oddOr, v);
    }
}

// ---------------- fused per-edge pass: decode, max(ea), raw deg, count ----------------
__global__ void k_prep(const void* __restrict__ ei, const float* __restrict__ ea) {
    bool is64 = (g_oddOr == 0u);
    const long long* p64 = (const long long*)ei;
    const int* p32 = (const int*)ei;
    float m = 0.f;
    for (int e = blockIdx.x * blockDim.x + threadIdx.x; e < NE;
         e += gridDim.x * blockDim.x) {
        int s, d;
        if (is64) { s = (int)p64[e]; d = (int)p64[NE + e]; }
        else      { s = p32[e];      d = p32[NE + e]; }
        g_src[e] = s;
        g_dst[e] = d;
        float a = ea[e];
        m = fmaxf(m, a);
        atomicAdd(&g_deg[d], a);
        atomicAdd(&g_count[d], 1);
    }
#pragma unroll
    for (int o = 16; o; o >>= 1) m = fmaxf(m, __shfl_xor_sync(0xffffffffu, m, o));
    if ((threadIdx.x & 31) == 0) atomicMax(&g_maxbits, __float_as_uint(m));
}

// ---------------- single-pass bucket allocation + node factors ----------------
__global__ void k_scanA() {
    __shared__ int wsum[SCAN_BLK / 32];
    __shared__ int sbase;
    int i = blockIdx.x * SCAN_BLK + threadIdx.x;
    int c = (i < NN) ? g_count[i] : 0;
    int lane = threadIdx.x & 31, wid = threadIdx.x >> 5;
    int v = c;
#pragma unroll
    for (int o = 1; o < 32; o <<= 1) {
        int u = __shfl_up_sync(0xffffffffu, v, o);
        if (lane >= o) v += u;
    }
    if (lane == 31) wsum[wid] = v;
    __syncthreads();
    if (wid == 0) {
        int w = (lane < SCAN_BLK / 32) ? wsum[lane] : 0;
#pragma unroll
        for (int o = 1; o < SCAN_BLK / 32; o <<= 1) {
            int u = __shfl_up_sync(0xffffffffu, w, o);
            if (lane >= o) w += u;
        }
        if (lane < SCAN_BLK / 32) wsum[lane] = w;
    }
    __syncthreads();
    if (threadIdx.x == 0) sbase = atomicAdd(&g_total, wsum[SCAN_BLK / 32 - 1]);
    __syncthreads();
    if (i < NN) {
        int excl = v - c + (wid > 0 ? wsum[wid - 1] : 0);
        g_rowptr[i] = sbase + excl;
        float invmax = 1.f / __uint_as_float(g_maxbits);
        float d = fmaf(g_deg[i], invmax, 1.f);
        g_dinv[i] = rsqrtf(d);
        g_invdeg[i] = 1.f / d;
    }
}

// ---------------- fill CSR: one packed 8B store per edge ----------------
__global__ void k_fill(const float* __restrict__ ea) {
    int e = blockIdx.x * blockDim.x + threadIdx.x;
    if (e >= NE) return;
    int s = g_src[e], d = g_dst[e];
    float invmax = 1.f / __uint_as_float(g_maxbits);
    float norm = g_dinv[s] * (ea[e] * invmax) * g_dinv[d];
    int pos = g_rowptr[d] + atomicAdd(&g_fill[d], 1);
    g_edge[pos] = (ull)(unsigned int)s | ((ull)__float_as_uint(norm) << 32);
}

// ---------------- 128xN-tiled fp32 GEMM; STOREH: write fp16 H, else fp32 H ----------------
template <int BN, int TN, int STOREH>
__global__ void k_gemm(const float* __restrict__ Aext, int useBufA,
                       const float* __restrict__ W, int M, int K, int reluIn) {
    __shared__ float As[16][132];
    __shared__ float Bs[16][BN + 4];
    const float* A = useBufA ? g_bufA : Aext;

    int tid = threadIdx.x;
    int tr = tid >> 4;
    int tc = tid & 15;
    int rowBase = blockIdx.y * 128;

    ull acc2[8][TN / 2];
#pragma unroll
    for (int i = 0; i < 8; i++)
#pragma unroll
        for (int j = 0; j < TN / 2; j++) acc2[i][j] = 0ull;

    for (int kt = 0; kt < K; kt += 16) {
#pragma unroll
        for (int idx = tid; idx < 512; idx += 256) {
            int r = idx >> 2;
            int c4 = (idx & 3) * 4;
            int ar = rowBase + r;
            float4 v = make_float4(0.f, 0.f, 0.f, 0.f);
            if (ar < M) v = *(const float4*)(A + (size_t)ar * K + kt + c4);
            if (reluIn) {
                v.x = fmaxf(v.x, 0.f); v.y = fmaxf(v.y, 0.f);
                v.z = fmaxf(v.z, 0.f); v.w = fmaxf(v.w, 0.f);
            }
            As[c4 + 0][r] = v.x; As[c4 + 1][r] = v.y;
            As[c4 + 2][r] = v.z; As[c4 + 3][r] = v.w;
        }
        constexpr int F4R = BN / 4;
#pragma unroll
        for (int idx = tid; idx < 16 * F4R; idx += 256) {
            int r = idx / F4R;
            int c = (idx % F4R) * 4;
            float4 v = *(const float4*)(W + (size_t)(kt + r) * BN + c);
            *(float4*)&Bs[r][c] = v;
        }
        __syncthreads();

#pragma unroll
        for (int kk = 0; kk < 16; kk++) {
            float a[8];
            *(float4*)&a[0] = *(const float4*)&As[kk][tr * 8];
            *(float4*)&a[4] = *(const float4*)&As[kk][tr * 8 + 4];
            ull bp[TN / 2];
#pragma unroll
            for (int j = 0; j < TN / 2; j++)
                bp[j] = *(const ull*)&Bs[kk][tc * TN + 2 * j];
#pragma unroll
            for (int i = 0; i < 8; i++) {
                ull aa = pack2(a[i], a[i]);
#pragma unroll
                for (int j = 0; j < TN / 2; j++) ffma2(acc2[i][j], aa, bp[j]);
            }
        }
        __syncthreads();
    }

#pragma unroll
    for (int i = 0; i < 8; i++) {
        int r = rowBase + tr * 8 + i;
        if (r >= M) continue;
        float o[TN];
#pragma unroll
        for (int j = 0; j < TN / 2; j++) unpack2(acc2[i][j], o[2 * j], o[2 * j + 1]);
        if (STOREH) {
            __half hh[TN];
#pragma unroll
            for (int j = 0; j < TN; j++) hh[j] = __float2half_rn(o[j]);
            char* dst = (char*)(g_h16 + (size_t)r * BN + tc * TN);
            if (TN == 8)      *(uint4*)dst = *(uint4*)hh;
            else if (TN == 4) *(uint2*)dst = *(uint2*)hh;
        } else {
            float* dst = g_h + (size_t)r * BN + tc * TN;
            if (TN == 8) {
                *(float4*)dst = *(float4*)&o[0];
                *(float4*)(dst + 4) = *(float4*)&o[4];
            } else if (TN == 4) {
                *(float4*)dst = *(float4*)&o[0];
            } else {
                *(float2*)dst = *(float2*)&o[0];
            }
        }
    }
}

// ---------------- fp16 gather: AGG(fp32) = H16[n]*invdeg + bias + sum norm*H16[src] ----------------
// VEC = chunks of 8 halves (16B) per node row. Each thread owns 8 features.
template <int VEC, int SHIFT>
__global__ void k_gather16(const float* __restrict__ bias) {
    int t = blockIdx.x * blockDim.x + threadIdx.x;
    if (t >= NN * VEC) return;
    int n = t >> SHIFT;
    int j = t & (VEC - 1);
    int beg = g_rowptr[n];
    int end = beg + g_count[n];
    const uint4* __restrict__ H = (const uint4*)g_h16;   // 16B = 8 halves
    const ull* __restrict__ edge = g_edge;

    float acc[8];
    {
        float id = g_invdeg[n];
        uint4 hv = H[(size_t)n * VEC + j];
        const __half2* h2 = (const __half2*)&hv;
        const float* b = bias + j * 8;
#pragma unroll
        for (int q = 0; q < 4; q++) {
            float2 f = __half22float2(h2[q]);
            acc[2 * q + 0] = fmaf(f.x, id, b[2 * q + 0]);
            acc[2 * q + 1] = fmaf(f.y, id, b[2 * q + 1]);
        }
    }

    int k = beg;
    for (; k + 4 <= end; k += 4) {
        ull e0 = edge[k], e1 = edge[k + 1], e2 = edge[k + 2], e3 = edge[k + 3];
        uint4 v0 = H[(size_t)(unsigned int)e0 * VEC + j];
        uint4 v1 = H[(size_t)(unsigned int)e1 * VEC + j];
        uint4 v2 = H[(size_t)(unsigned int)e2 * VEC + j];
        uint4 v3 = H[(size_t)(unsigned int)e3 * VEC + j];
        float n0 = __uint_as_float((unsigned int)(e0 >> 32));
        float n1 = __uint_as_float((unsigned int)(e1 >> 32));
        float n2 = __uint_as_float((unsigned int)(e2 >> 32));
        float n3 = __uint_as_float((unsigned int)(e3 >> 32));
        const __half2* p0 = (const __half2*)&v0;
        const __half2* p1 = (const __half2*)&v1;
        const __half2* p2 = (const __half2*)&v2;
        const __half2* p3 = (const __half2*)&v3;
#pragma unroll
        for (int q = 0; q < 4; q++) {
            float2 f0 = __half22float2(p0[q]);
            float2 f1 = __half22float2(p1[q]);
            float2 f2 = __half22float2(p2[q]);
            float2 f3 = __half22float2(p3[q]);
            acc[2 * q + 0] = fmaf(n0, f0.x, acc[2 * q + 0]);
            acc[2 * q + 1] = fmaf(n0, f0.y, acc[2 * q + 1]);
            acc[2 * q + 0] = fmaf(n1, f1.x, acc[2 * q + 0]);
            acc[2 * q + 1] = fmaf(n1, f1.y, acc[2 * q + 1]);
            acc[2 * q + 0] = fmaf(n2, f2.x, acc[2 * q + 0]);
            acc[2 * q + 1] = fmaf(n2, f2.y, acc[2 * q + 1]);
            acc[2 * q + 0] = fmaf(n3, f3.x, acc[2 * q + 0]);
            acc[2 * q + 1] = fmaf(n3, f3.y, acc[2 * q + 1]);
        }
    }
    for (; k < end; k++) {
        ull e0 = edge[k];
        float nm = __uint_as_float((unsigned int)(e0 >> 32));
        uint4 v0 = H[(size_t)(unsigned int)e0 * VEC + j];
        const __half2* p0 = (const __half2*)&v0;
#pragma unroll
        for (int q = 0; q < 4; q++) {
            float2 f0 = __half22float2(p0[q]);
            acc[2 * q + 0] = fmaf(nm, f0.x, acc[2 * q + 0]);
            acc[2 * q + 1] = fmaf(nm, f0.y, acc[2 * q + 1]);
        }
    }

    float* dst = g_bufA + ((size_t)n * VEC + j) * 8;
    *(float4*)dst = *(float4*)&acc[0];
    *(float4*)(dst + 4) = *(float4*)&acc[4];
}

// ---------------- layer-3 gather (fp32 H) fused with relu + mean-pool ----------------
__global__ void k_gather_pool(const float* __restrict__ bias,
                              const void* __restrict__ batch) {
    int t = blockIdx.x * blockDim.x + threadIdx.x;
    if (t >= NN * 8) return;
    int n = t >> 3;
    int j = t & 7;
    int beg = g_rowptr[n];
    int end = beg + g_count[n];
    const float4* __restrict__ H4 = (const float4*)g_h;
    const ull* __restrict__ edge = g_edge;

    float id = g_invdeg[n];
    float4 b = *(const float4*)(bias + j * 4);
    float4 hv = H4[(size_t)n * 8 + j];
    float4 acc;
    acc.x = fmaf(hv.x, id, b.x);
    acc.y = fmaf(hv.y, id, b.y);
    acc.z = fmaf(hv.z, id, b.z);
    acc.w = fmaf(hv.w, id, b.w);

    int k = beg;
    for (; k + 4 <= end; k += 4) {
        ull e0 = edge[k], e1 = edge[k + 1], e2 = edge[k + 2], e3 = edge[k + 3];
        float n0 = __uint_as_float((unsigned int)(e0 >> 32));
        float n1 = __uint_as_float((unsigned int)(e1 >> 32));
        float n2 = __uint_as_float((unsigned int)(e2 >> 32));
        float n3 = __uint_as_float((unsigned int)(e3 >> 32));
        float4 v0 = H4[(size_t)(unsigned int)e0 * 8 + j];
        float4 v1 = H4[(size_t)(unsigned int)e1 * 8 + j];
        float4 v2 = H4[(size_t)(unsigned int)e2 * 8 + j];
        float4 v3 = H4[(size_t)(unsigned int)e3 * 8 + j];
        acc.x = fmaf(n0, v0.x, acc.x); acc.y = fmaf(n0, v0.y, acc.y);
        acc.z = fmaf(n0, v0.z, acc.z); acc.w = fmaf(n0, v0.w, acc.w);
        acc.x = fmaf(n1, v1.x, acc.x); acc.y = fmaf(n1, v1.y, acc.y);
        acc.z = fmaf(n1, v1.z, acc.z); acc.w = fmaf(n1, v1.w, acc.w);
        acc.x = fmaf(n2, v2.x, acc.x); acc.y = fmaf(n2, v2.y, acc.y);
        acc.z = fmaf(n2, v2.z, acc.z); acc.w = fmaf(n2, v2.w, acc.w);
        acc.x = fmaf(n3, v3.x, acc.x); acc.y = fmaf(n3, v3.y, acc.y);
        acc.z = fmaf(n3, v3.z, acc.z); acc.w = fmaf(n3, v3.w, acc.w);
    }
    for (; k < end; k++) {
        ull e0 = edge[k];
        float nm = __uint_as_float((unsigned int)(e0 >> 32));
        float4 v = H4[(size_t)(unsigned int)e0 * 8 + j];
        acc.x = fmaf(nm, v.x, acc.x);
        acc.y = fmaf(nm, v.y, acc.y);
        acc.z = fmaf(nm, v.z, acc.z);
        acc.w = fmaf(nm, v.w, acc.w);
    }

    int g;
    if (g_oddOr == 0u) g = (int)((const long long*)batch)[n];
    else               g = ((const int*)batch)[n];
    float* p = &g_pool[g * 32 + j * 4];
    atomicAdd(p + 0, fmaxf(acc.x, 0.f));
    atomicAdd(p + 1, fmaxf(acc.y, 0.f));
    atomicAdd(p + 2, fmaxf(acc.z, 0.f));
    atomicAdd(p + 3, fmaxf(acc.w, 0.f));
    if (j == 0) atomicAdd(&g_cnt[g], 1.f);
}

// ---------------- head ----------------
__global__ void k_out(const float* __restrict__ Wl, const float* __restrict__ bl,
                      float* __restrict__ out) {
    __shared__ float pooled[32];
    int g = blockIdx.x;
    if (threadIdx.x < 32) {
        float c = g_cnt[g];
        pooled[threadIdx.x] = g_pool[g * 32 + threadIdx.x] / fmaxf(c, 1.f);
    }
    __syncthreads();
    int o = threadIdx.x;  // 768 threads
    float acc = bl[o];
#pragma unroll
    for (int c = 0; c < 32; c++) acc = fmaf(pooled[c], Wl[c * 768 + o], acc);
    out[(size_t)g * 768 + o] = acc;
}

// ---------------- launch (fork/join: CSR build || layer-1 GEMM) ----------------
extern "C" void kernel_launch(void* const* d_in, const int* in_sizes, int n_in,
                              void* d_out, int out_size) {
    const float* x = (const float*)d_in[0];
    const void* ei = d_in[1];
    const float* ea = (const float*)d_in[2];
    const void* batch = d_in[3];
    const float* W1 = (const float*)d_in[4];
    const float* b1 = (const float*)d_in[5];
    const float* W2 = (const float*)d_in[6];
    const float* b2 = (const float*)d_in[7];
    const float* W3 = (const float*)d_in[8];
    const float* b3 = (const float*)d_in[9];
    const float* Wl = (const float*)d_in[10];
    const float* bl = (const float*)d_in[11];
    float* out = (float*)d_out;

    static cudaStream_t s2 = nullptr;
    static cudaEvent_t evFork = nullptr, evJoin = nullptr;
    if (!s2) {
        cudaStreamCreateWithFlags(&s2, cudaStreamNonBlocking);
        cudaEventCreateWithFlags(&evFork, cudaEventDisableTiming);
        cudaEventCreateWithFlags(&evJoin, cudaEventDisableTiming);
    }
    cudaStream_t s0 = cudaStreamPerThread;

    // Fork: side stream runs layer-1 GEMM (depends only on x, W1) -> fp16 H.
    cudaEventRecord(evFork, s0);
    cudaStreamWaitEvent(s2, evFork, 0);
    {
        dim3 grid(1, (NN + 127) / 128);
        k_gemm<128, 8, 1><<<grid, 256, 0, s2>>>(x, 0, W1, NN, 128, /*relu=*/0);
        cudaEventRecord(evJoin, s2);
    }

    // Main stream: CSR build chain.
    k_init<<<(NN + 255) / 256, 256, 0, s0>>>((const unsigned int*)ei);
    k_prep<<<512, 256, 0, s0>>>(ei, ea);
    k_scanA<<<NBLK, SCAN_BLK, 0, s0>>>();
    k_fill<<<(NE + 255) / 256, 256, 0, s0>>>(ea);

    // Join: gather-1 needs both H16 (s2) and CSR (s0).
    cudaStreamWaitEvent(s0, evJoin, 0);
    k_gather16<16, 4><<<(NN * 16 + 255) / 256, 256, 0, s0>>>(b1);

    // Layer 2: relu(bufA) @ W2 -> fp16 H; fp16 gather -> bufA
    {
        dim3 grid(1, (NN + 127) / 128);
        k_gemm<64, 4, 1><<<grid, 256, 0, s0>>>(nullptr, 1, W2, NN, 128, /*relu=*/1);
        k_gather16<8, 3><<<(NN * 8 + 255) / 256, 256, 0, s0>>>(b2);
    }
    // Layer 3: relu(bufA) @ W3 -> fp32 H; fp32 gather fused with pool
    {
        dim3 grid(1, (NN + 127) / 128);
        k_gemm<32, 2, 0><<<grid, 256, 0, s0>>>(nullptr, 1, W3, NN, 64, /*relu=*/1);
        k_gather_pool<<<(NN * 8 + 255) / 256, 256, 0, s0>>>(b3, batch);
    }
    k_out<<<NG, 768, 0, s0>>>(Wl, bl, out);
}